// round 13
// baseline (speedup 1.0000x reference)
#include <cuda_runtime.h>
#include <cuda_bf16.h>
#include <math.h>

typedef __nv_bfloat16 bf16;
typedef long long ll;

#define NHEAD  8
#define DMODEL 1024
#define DT     256
#define BATCH  32
#define LLEN   1024

// ---------------------------------------------------------------------------
// Static arenas. hi/lo bf16 twins share offsets.
// QT,KT,VT,PRT contiguous, stride 8486912. WCQ..WFC stride 851968.
// WQT/WKT/WVT stride 2097152. QB/KB/VB stride 8388608. QS/KS stride 16777216.
// ---------------------------------------------------------------------------
#define O_QT   0LL            // (32, 1036, 256) padded transposed inputs
#define O_KT   8486912LL
#define O_VT   16973824LL
#define O_PRT  25460736LL     // (32, 1036, 256) proj output, transposed+padded
#define O_WCQ  33947648LL     // conv weights repacked (13, 256, 256)
#define O_WCK  34799616LL
#define O_WCV  35651584LL
#define O_WFC  36503552LL
#define O_WQT  37355520LL     // head weights transposed (8, 256, 1024)
#define O_WKT  39452672LL
#define O_WVT  41549824LL
#define O_PJW  43646976LL     // proj weight (1024, 2048) split only
#define O_QB   45744128LL     // conv outputs (32, 256, 1024)
#define O_KB   54132736LL
#define O_VB   62521344LL
#define O_QS   70909952LL     // (8, 32, 256, 256)
#define O_KS   87687168LL
#define O_VST  104464384LL    // vs transposed (8, 32, 256(d), 256(t))
#define O_ATT  121241600LL
#define O_CAT  138018816LL    // (32, 256, 2048)
#define BF_TOTAL 154796032LL

#define F_SC   0LL
#define F_FC   16777216LL
#define F_BIAS 25165824LL     // packed conv biases (3 x 256)
#define F_TOTAL 25166848LL

__device__ __align__(1024) bf16  g_bh[BF_TOTAL];
__device__ __align__(1024) bf16  g_bl[BF_TOTAL];
__device__ __align__(1024) float g_fs[F_TOTAL];

// ---------------------------------------------------------------------------
// helpers (plain sm_80+ PTX: cp.async, ldmatrix, mma.sync)
// ---------------------------------------------------------------------------
__device__ __forceinline__ unsigned smem_u32(const void* p) {
    unsigned a;
    asm("{ .reg .u64 t; cvta.to.shared.u64 t, %1; cvt.u32.u64 %0, t; }"
        : "=r"(a) : "l"(p));
    return a;
}
__device__ __forceinline__ void cp16(unsigned dst, const void* src) {
    asm volatile("cp.async.cg.shared.global [%0], [%1], 16;"
                 :: "r"(dst), "l"(src) : "memory");
}
__device__ __forceinline__ void cp_commit() {
    asm volatile("cp.async.commit_group;" ::: "memory");
}
template <int N>
__device__ __forceinline__ void cp_wait() {
    asm volatile("cp.async.wait_group %0;" :: "n"(N) : "memory");
}
__device__ __forceinline__ void ldsm4(unsigned r[4], unsigned addr) {
    asm volatile("ldmatrix.sync.aligned.m8n8.x4.shared.b16 {%0,%1,%2,%3}, [%4];"
                 : "=r"(r[0]), "=r"(r[1]), "=r"(r[2]), "=r"(r[3]) : "r"(addr));
}
__device__ __forceinline__ void mma16816(float* c, const unsigned a[4],
                                         unsigned b0, unsigned b1) {
    asm volatile(
        "mma.sync.aligned.m16n8k16.row.col.f32.bf16.bf16.f32 "
        "{%0,%1,%2,%3}, {%4,%5,%6,%7}, {%8,%9}, {%0,%1,%2,%3};"
        : "+f"(c[0]), "+f"(c[1]), "+f"(c[2]), "+f"(c[3])
        : "r"(a[0]), "r"(a[1]), "r"(a[2]), "r"(a[3]), "r"(b0), "r"(b1));
}
__device__ __forceinline__ void split2(float x, bf16& h, bf16& l) {
    h = __float2bfloat16(x);
    l = __float2bfloat16(x - __bfloat162float(h));
}

// ---------------------------------------------------------------------------
// Universal split-bf16 NT GEMM with taps and 3-level batching:
//   z = (z3*Z1 + z1)*Z2 + z2
//   C[m,n] = alpha * sum_t sum_k A[t][m,k] * B[t][n,k] + bias_m[z1*bias_z + m]
// CTA tile 128x128, K-chunk 32, 2 stages, 2 CTAs/SM, 8 warps (4m x 2n).
// ---------------------------------------------------------------------------
#define STG   40960        // bytes per stage
#define SUBT  10240        // bytes per sub-tile
#define GSMEM (2 * STG)

__global__ __launch_bounds__(256, 2)
void gemm_tc(
    const bf16* __restrict__ Ahi, const bf16* __restrict__ Alo,
    const bf16* __restrict__ Bhi, const bf16* __restrict__ Blo,
    float* __restrict__ Cf, bf16* __restrict__ Chi, bf16* __restrict__ Clo,
    int lda, int ldb, int ldc,
    ll a1, ll a2, ll b1, ll b2, ll c1, ll c2,
    ll a3, ll b3, ll c3,
    ll a_tap, ll b_tap, int kc_per_tap, int taps, int Z1, int Z2,
    float alpha, const float* __restrict__ bias_m, ll bias_z)
{
    extern __shared__ __align__(128) char smem[];
    const unsigned sb0 = smem_u32(smem);
    const int tid = threadIdx.x;
    const int warp = tid >> 5, lane = tid & 31;
    const int z = blockIdx.z;
    const int zz = Z1 * Z2;
    const int z3 = z / zz;
    const int rem = z - z3 * zz;
    const int z1 = rem / Z2, z2 = rem - z1 * Z2;
    const int m0 = blockIdx.y * 128, n0 = blockIdx.x * 128;

    const ll aoff = (ll)z3 * a3 + (ll)z1 * a1 + (ll)z2 * a2 + (ll)m0 * lda;
    const ll boff = (ll)z3 * b3 + (ll)z1 * b1 + (ll)z2 * b2 + (ll)n0 * ldb;
    const bf16* pAh = Ahi + aoff;
    const bf16* pAl = Alo + aoff;
    const bf16* pBh = Bhi + boff;
    const bf16* pBl = Blo + boff;

    // per-thread cp.async indices: 512 x 16B chunks per sub-tile
    const int ld_row = tid >> 2;          // 0..63  (+64 on second pass)
    const int ld_c16 = tid & 3;           // 16B column within 64B row
    const unsigned ld_off0 = (unsigned)(ld_row * 80 + ld_c16 * 16);
    const unsigned ld_off1 = (unsigned)((ld_row + 64) * 80 + ld_c16 * 16);

    float acc[2][8][4];
#pragma unroll
    for (int a = 0; a < 2; a++)
#pragma unroll
        for (int b = 0; b < 8; b++)
#pragma unroll
            for (int c = 0; c < 4; c++) acc[a][b][c] = 0.f;

    const int NC = kc_per_tap * taps;

    auto issue = [&](int i) {
        const int t  = (taps == 1) ? 0 : (i / kc_per_tap);
        const int kc = i - t * kc_per_tap;
        const ll ao = (ll)t * a_tap + (ll)kc * 32 + (ll)ld_c16 * 8;
        const ll bo = (ll)t * b_tap + (ll)kc * 32 + (ll)ld_c16 * 8;
        const unsigned s = sb0 + (i & 1) * STG;
        const ll ar0 = (ll)ld_row * lda, ar1 = (ll)(ld_row + 64) * lda;
        const ll br0 = (ll)ld_row * ldb, br1 = (ll)(ld_row + 64) * ldb;
        cp16(s + ld_off0,             pAh + ao + ar0);
        cp16(s + ld_off1,             pAh + ao + ar1);
        cp16(s + SUBT + ld_off0,      pAl + ao + ar0);
        cp16(s + SUBT + ld_off1,      pAl + ao + ar1);
        cp16(s + 2 * SUBT + ld_off0,  pBh + bo + br0);
        cp16(s + 2 * SUBT + ld_off1,  pBh + bo + br1);
        cp16(s + 3 * SUBT + ld_off0,  pBl + bo + br0);
        cp16(s + 3 * SUBT + ld_off1,  pBl + bo + br1);
        cp_commit();
    };

    const int wm = (warp & 3) * 32;       // warp m origin in tile
    const int wn = (warp >> 2) * 64;      // warp n origin
    const int li = lane & 7, lj = lane >> 3;
    const int a_row_add = li + ((lj & 1) << 3);
    const unsigned a_col = (unsigned)((lj >> 1) << 4);
    const int b_row_add = li + ((lj >> 1) << 3);
    const unsigned b_col = (unsigned)((lj & 1) << 4);

    issue(0);
    for (int i = 0; i < NC; i++) {
        if (i + 1 < NC) { issue(i + 1); cp_wait<1>(); }
        else            { cp_wait<0>(); }
        __syncthreads();

        const unsigned s = sb0 + (i & 1) * STG;
#pragma unroll
        for (int kk = 0; kk < 2; kk++) {
            unsigned ah[2][4], al[2][4];
#pragma unroll
            for (int mb = 0; mb < 2; mb++) {
                const unsigned ar = (unsigned)((wm + mb * 16 + a_row_add) * 80)
                                    + (unsigned)(kk * 32) + a_col;
                ldsm4(ah[mb], s + ar);
                ldsm4(al[mb], s + SUBT + ar);
            }
#pragma unroll
            for (int nb = 0; nb < 4; nb++) {
                const unsigned br = (unsigned)((wn + nb * 16 + b_row_add) * 80)
                                    + (unsigned)(kk * 32) + b_col;
                unsigned bh[4], blr[4];
                ldsm4(bh,  s + 2 * SUBT + br);
                ldsm4(blr, s + 3 * SUBT + br);
#pragma unroll
                for (int mb = 0; mb < 2; mb++) {
#pragma unroll
                    for (int h = 0; h < 2; h++) {
                        float* c = acc[mb][nb * 2 + h];
                        mma16816(c, ah[mb], bh[2 * h],  bh[2 * h + 1]);
                        mma16816(c, ah[mb], blr[2 * h], blr[2 * h + 1]);
                        mma16816(c, al[mb], bh[2 * h],  bh[2 * h + 1]);
                    }
                }
            }
        }
        __syncthreads();
    }

    // ---- epilogue ----
    const ll coff = (ll)z3 * c3 + (ll)z1 * c1 + (ll)z2 * c2;
    const ll boffb = (ll)z1 * bias_z;
    const int g = lane >> 2, qd = lane & 3;
#pragma unroll
    for (int mb = 0; mb < 2; mb++) {
        const int r0 = m0 + wm + mb * 16 + g;
        const float bm0 = bias_m ? bias_m[boffb + r0] : 0.f;
        const float bm1 = bias_m ? bias_m[boffb + r0 + 8] : 0.f;
#pragma unroll
        for (int nf = 0; nf < 8; nf++) {
            const int col = n0 + wn + nf * 8 + qd * 2;
            const float* c = acc[mb][nf];
            float v00 = c[0] * alpha + bm0, v01 = c[1] * alpha + bm0;
            float v10 = c[2] * alpha + bm1, v11 = c[3] * alpha + bm1;
            const ll o0 = coff + (ll)r0 * ldc + col;
            const ll o1 = coff + (ll)(r0 + 8) * ldc + col;
            if (Cf) {
                *reinterpret_cast<float2*>(Cf + o0) = make_float2(v00, v01);
                *reinterpret_cast<float2*>(Cf + o1) = make_float2(v10, v11);
            }
            if (Chi) {
                bf16 h0, l0, h1, l1;
                split2(v00, h0, l0); split2(v01, h1, l1);
                *reinterpret_cast<__nv_bfloat162*>(Chi + o0) = __nv_bfloat162(h0, h1);
                *reinterpret_cast<__nv_bfloat162*>(Clo + o0) = __nv_bfloat162(l0, l1);
                split2(v10, h0, l0); split2(v11, h1, l1);
                *reinterpret_cast<__nv_bfloat162*>(Chi + o1) = __nv_bfloat162(h0, h1);
                *reinterpret_cast<__nv_bfloat162*>(Clo + o1) = __nv_bfloat162(l0, l1);
            }
        }
    }
}

// ---------------------------------------------------------------------------
// Merged preps (5 launches total so the conv GEMM is launch #6 for ncu).
// ---------------------------------------------------------------------------

// 1. zero halo pad rows of QT,KT,VT,PRT (contiguous) + pack conv biases
__global__ __launch_bounds__(256) void zero_pads_bias(
    bf16* __restrict__ ph, bf16* __restrict__ pl,
    const float* __restrict__ b0, const float* __restrict__ b1,
    const float* __restrict__ b2, float* __restrict__ ob)
{
    if (blockIdx.x >= 1536) {
        int i = (blockIdx.x - 1536) * 256 + threadIdx.x;   // 0..767
        int sel = i >> 8, c = i & 255;
        ob[i] = (sel == 0 ? b0 : sel == 1 ? b1 : b2)[c];
        return;
    }
    int idx = blockIdx.x * 256 + threadIdx.x;          // < 393216
    int b = idx / 3072, rem = idx % 3072;              // b in 0..127
    int r12 = rem >> 8, c = rem & 255;
    int row = (r12 < 6) ? r12 : (1024 + r12);
    size_t o = (size_t)b * 265216 + (size_t)row * 256 + c;
    ph[o] = __float2bfloat16(0.f);
    pl[o] = __float2bfloat16(0.f);
}

// 2. merged q/k/v input transpose+split: (32,256,1024) -> (32,1036,256)
__global__ __launch_bounds__(256) void tr_inputs(
    const float* __restrict__ q, const float* __restrict__ k,
    const float* __restrict__ v, bf16* __restrict__ oh, bf16* __restrict__ ol)
{
    __shared__ float t[32][33];
    const int z = blockIdx.z;                 // 0..95
    const int sel = z >> 5, b = z & 31;
    const float* in = (sel == 0 ? q : sel == 1 ? k : v) + (size_t)b * 262144;
    const size_t ob = (size_t)sel * 8486912 + (size_t)b * 265216;
    const int c0 = blockIdx.x * 32, r0 = blockIdx.y * 32;   // c in 0..1023, r in 0..255
    const int tx = threadIdx.x & 31, ty = threadIdx.x >> 5;
#pragma unroll
    for (int j = 0; j < 4; j++)
        t[ty + 8 * j][tx] = in[(size_t)(r0 + ty + 8 * j) * 1024 + c0 + tx];
    __syncthreads();
#pragma unroll
    for (int j = 0; j < 4; j++) {
        float x = t[tx][ty + 8 * j];
        bf16 h, l; split2(x, h, l);
        size_t o = ob + (size_t)(c0 + ty + 8 * j + 6) * 256 + r0 + tx;
        oh[o] = h; ol[o] = l;
    }
}

// 3. merged head-weight transpose+split: (8,1024,256) -> (8,256,1024)
__global__ __launch_bounds__(256) void tr_weights(
    const float* __restrict__ wq, const float* __restrict__ wk,
    const float* __restrict__ wv, bf16* __restrict__ oh, bf16* __restrict__ ol)
{
    __shared__ float t[32][33];
    const int z = blockIdx.z;                 // 0..23
    const int sel = z >> 3, h = z & 7;
    const float* in = (sel == 0 ? wq : sel == 1 ? wk : wv) + (size_t)h * 262144;
    const size_t ob = (size_t)sel * 2097152 + (size_t)h * 262144;
    const int c0 = blockIdx.x * 32, r0 = blockIdx.y * 32;   // c in 0..255, r in 0..1023
    const int tx = threadIdx.x & 31, ty = threadIdx.x >> 5;
#pragma unroll
    for (int j = 0; j < 4; j++)
        t[ty + 8 * j][tx] = in[(size_t)(r0 + ty + 8 * j) * 256 + c0 + tx];
    __syncthreads();
#pragma unroll
    for (int j = 0; j < 4; j++) {
        float x = t[tx][ty + 8 * j];
        bf16 hh, l; split2(x, hh, l);
        size_t o = ob + (size_t)(c0 + ty + 8 * j) * 1024 + r0 + tx;
        oh[o] = hh; ol[o] = l;
    }
}

// 4. merged conv-weight repack (4 tensors): out[t][o][c] = w[o][c][t]
__global__ __launch_bounds__(256) void conv_w_prep4(
    const float* __restrict__ w0, const float* __restrict__ w1,
    const float* __restrict__ w2, const float* __restrict__ w3,
    bf16* __restrict__ oh, bf16* __restrict__ ol)
{
    int idx = blockIdx.x * 256 + threadIdx.x;          // < 3407872
    int sel = idx / 851968, r = idx - sel * 851968;
    int t = r >> 16, rem = r & 65535;
    int o = rem >> 8, c = rem & 255;
    const float* w = sel == 0 ? w0 : sel == 1 ? w1 : sel == 2 ? w2 : w3;
    float x = w[(size_t)(o * 256 + c) * 13 + t];
    bf16 h, l; split2(x, h, l);
    oh[idx] = h; ol[idx] = l;
}

// 5. split only (proj weight)
__global__ __launch_bounds__(256) void split_k(
    const float* __restrict__ in, bf16* __restrict__ oh, bf16* __restrict__ ol, int n)
{
    int i = blockIdx.x * 256 + threadIdx.x;
    if (i < n) { bf16 h, l; split2(in[i], h, l); oh[i] = h; ol[i] = l; }
}

// ---------------------------------------------------------------------------
// softmax over last axis (256); fp32 attn to d_out AND split pair to arena.
// ---------------------------------------------------------------------------
__global__ __launch_bounds__(256) void softmax_split(
    const float* __restrict__ scores, float* __restrict__ attn,
    bf16* __restrict__ ah, bf16* __restrict__ al)
{
    const int row  = blockIdx.x * 8 + (threadIdx.x >> 5);
    const int lane = threadIdx.x & 31;
    const float* s = scores + (size_t)row * 256;

    float v[8];
    float mx = -1e30f;
#pragma unroll
    for (int j = 0; j < 8; j++) { v[j] = s[lane + 32 * j]; mx = fmaxf(mx, v[j]); }
#pragma unroll
    for (int o = 16; o; o >>= 1) mx = fmaxf(mx, __shfl_xor_sync(0xffffffffu, mx, o));
    float sum = 0.f;
#pragma unroll
    for (int j = 0; j < 8; j++) { v[j] = expf(v[j] - mx); sum += v[j]; }
#pragma unroll
    for (int o = 16; o; o >>= 1) sum += __shfl_xor_sync(0xffffffffu, sum, o);
    const float inv = 1.f / sum;

    float* a  = attn + (size_t)row * 256;
    bf16* hh = ah + (size_t)row * 256;
    bf16* ll_ = al + (size_t)row * 256;
#pragma unroll
    for (int j = 0; j < 8; j++) {
        float p = v[j] * inv;
        a[lane + 32 * j] = p;
        bf16 h, l; split2(p, h, l);
        hh[lane + 32 * j] = h; ll_[lane + 32 * j] = l;
    }
}

// ---------------------------------------------------------------------------
// residual + LayerNorm (ddof=1, eps added to sigma)
// ---------------------------------------------------------------------------
__global__ __launch_bounds__(256) void ln_kernel(
    const float* __restrict__ fc, const float* __restrict__ q,
    const float* __restrict__ ga, const float* __restrict__ gb,
    float* __restrict__ out)
{
    const int row = blockIdx.x;
    const float* f  = fc + (size_t)row * DMODEL;
    const float* qq = q  + (size_t)row * DMODEL;
    const int tid = threadIdx.x;

    float zv[4];
    float s = 0.f, ss = 0.f;
#pragma unroll
    for (int j = 0; j < 4; j++) {
        float zz = f[tid + 256 * j] + qq[tid + 256 * j];
        zv[j] = zz; s += zz; ss += zz * zz;
    }
    __shared__ float rs[8], rss[8];
#pragma unroll
    for (int o = 16; o; o >>= 1) {
        s  += __shfl_xor_sync(0xffffffffu, s, o);
        ss += __shfl_xor_sync(0xffffffffu, ss, o);
    }
    if ((tid & 31) == 0) { rs[tid >> 5] = s; rss[tid >> 5] = ss; }
    __syncthreads();
    if (tid < 32) {
        float a = (tid < 8) ? rs[tid] : 0.f;
        float b = (tid < 8) ? rss[tid] : 0.f;
#pragma unroll
        for (int o = 4; o; o >>= 1) {
            a += __shfl_xor_sync(0xffffffffu, a, o);
            b += __shfl_xor_sync(0xffffffffu, b, o);
        }
        if (tid == 0) { rs[0] = a; rss[0] = b; }
    }
    __syncthreads();
    const float mu  = rs[0] * (1.f / DMODEL);
    const float var = (rss[0] - (float)DMODEL * mu * mu) * (1.f / (DMODEL - 1));
    const float inv = 1.f / (sqrtf(fmaxf(var, 0.f)) + 1e-3f);
    float* o_ = out + (size_t)row * DMODEL;
#pragma unroll
    for (int j = 0; j < 4; j++) {
        const int col = tid + 256 * j;
        o_[col] = (zv[j] - mu) * inv * ga[col] + gb[col];
    }
}

// ---------------------------------------------------------------------------
extern "C" void kernel_launch(void* const* d_in, const int* in_sizes, int n_in,
                              void* d_out, int out_size)
{
    const float* q    = (const float*)d_in[0];
    const float* k    = (const float*)d_in[1];
    const float* v    = (const float*)d_in[2];
    const float* cq_w = (const float*)d_in[3];
    const float* cq_b = (const float*)d_in[4];
    const float* ck_w = (const float*)d_in[5];
    const float* ck_b = (const float*)d_in[6];
    const float* cv_w = (const float*)d_in[7];
    const float* cv_b = (const float*)d_in[8];
    const float* w_qs = (const float*)d_in[9];
    const float* w_ks = (const float*)d_in[10];
    const float* w_vs = (const float*)d_in[11];
    const float* pj_w = (const float*)d_in[12];
    const float* pj_b = (const float*)d_in[13];
    const float* fc_w = (const float*)d_in[14];
    const float* fc_b = (const float*)d_in[15];
    const float* ln_a = (const float*)d_in[16];
    const float* ln_b = (const float*)d_in[17];

    bf16 *bh = nullptr, *bl = nullptr; float* fs = nullptr;
    cudaGetSymbolAddress((void**)&bh, g_bh);
    cudaGetSymbolAddress((void**)&bl, g_bl);
    cudaGetSymbolAddress((void**)&fs, g_fs);

    cudaFuncSetAttribute(gemm_tc, cudaFuncAttributeMaxDynamicSharedMemorySize, GSMEM);

    float* out  = (float*)d_out;
    float* attn = out + (size_t)BATCH * DT * LLEN;

    // ---- preps: exactly 5 launches (ncu -s 5 profiles launch #6 = conv GEMM)
    zero_pads_bias<<<1539, 256>>>(bh + O_QT, bl + O_QT,
                                  cq_b, ck_b, cv_b, fs + F_BIAS);       // 1
    tr_inputs<<<dim3(32, 8, 96), 256>>>(q, k, v, bh + O_QT, bl + O_QT); // 2
    tr_weights<<<dim3(8, 32, 24), 256>>>(w_qs, w_ks, w_vs,
                                         bh + O_WQT, bl + O_WQT);       // 3
    conv_w_prep4<<<13312, 256>>>(cq_w, ck_w, cv_w, fc_w,
                                 bh + O_WCQ, bl + O_WCQ);               // 4
    split_k<<<8192, 256>>>(pj_w, bh + O_PJW, bl + O_PJW, 2097152);      // 5

    // ---- 6. conv q/k/v MERGED: z1 = conv idx (0..2), z2 = batch ----
    gemm_tc<<<dim3(8, 2, 96), 256, GSMEM>>>(
        bh + O_WCQ, bl + O_WCQ, bh + O_QT, bl + O_QT,
        nullptr, bh + O_QB, bl + O_QB, 256, 256, 1024,
        851968, 0, 8486912, 265216, 8388608, 262144,
        0, 0, 0,
        65536, 256, 8, 13, 3, 32, 1.f, fs + F_BIAS, 256);

    // ---- 7. Q + K head projections MERGED: z3 = {q,k}, z1 = h, z2 = b ----
    gemm_tc<<<dim3(2, 2, 512), 256, GSMEM>>>(
        bh + O_QB, bl + O_QB, bh + O_WQT, bl + O_WQT,
        nullptr, bh + O_QS, bl + O_QS, 1024, 1024, 256,
        0, 262144, 262144, 0, 2097152, 65536,
        8388608, 2097152, 16777216,
        0, 0, 32, 1, 8, 32, 1.f, nullptr, 0);

    // ---- 8. V head projection, transposed output ----
    gemm_tc<<<dim3(2, 2, 256), 256, GSMEM>>>(
        bh + O_WVT, bl + O_WVT, bh + O_VB, bl + O_VB,
        nullptr, bh + O_VST, bl + O_VST, 1024, 1024, 256,
        262144, 0, 0, 262144, 2097152, 65536,
        0, 0, 0,
        0, 0, 32, 1, 8, 32, 1.f, nullptr, 0);

    // ---- 9. scores = qs . ks^T / 32 -> fp32 ----
    gemm_tc<<<dim3(2, 2, 256), 256, GSMEM>>>(
        bh + O_QS, bl + O_QS, bh + O_KS, bl + O_KS,
        fs + F_SC, nullptr, nullptr, 256, 256, 256,
        2097152, 65536, 2097152, 65536, 2097152, 65536,
        0, 0, 0,
        0, 0, 8, 1, 8, 32, 1.f / 32.f, nullptr, 0);

    // ---- 10. softmax -> attns (d_out) + split arena ----
    softmax_split<<<8192, 256>>>(fs + F_SC, attn, bh + O_ATT, bl + O_ATT);

    // ---- 11. out = attn . vsT^T -> cat (B, 256, 2048) ----
    gemm_tc<<<dim3(2, 2, 256), 256, GSMEM>>>(
        bh + O_ATT, bl + O_ATT, bh + O_VST, bl + O_VST,
        nullptr, bh + O_CAT, bl + O_CAT, 256, 256, 2048,
        2097152, 65536, 2097152, 65536, 256, 524288,
        0, 0, 0,
        0, 0, 8, 1, 8, 32, 1.f, nullptr, 0);

    // ---- 12. proj, transposed: C[dm][t] -> prT (pad row offset 6) ----
    gemm_tc<<<dim3(2, 8, 32), 256, GSMEM>>>(
        bh + O_PJW, bl + O_PJW, bh + O_CAT, bl + O_CAT,
        nullptr, bh + O_PRT + 1536, bl + O_PRT + 1536, 2048, 2048, 256,
        0, 0, 0, 524288, 0, 265216,
        0, 0, 0,
        0, 0, 64, 1, 1, 32, 1.f, pj_b, 0);

    // ---- 13. fc conv: M=256(o), N=1024(l), K=256 x 13 -> fp32 ----
    gemm_tc<<<dim3(8, 2, 32), 256, GSMEM>>>(
        bh + O_WFC, bl + O_WFC, bh + O_PRT, bl + O_PRT,
        fs + F_FC, nullptr, nullptr, 256, 256, 1024,
        0, 0, 0, 265216, 0, 262144,
        0, 0, 0,
        65536, 256, 8, 13, 1, 32, 1.f, fc_b, 0);

    // ---- 14. residual + LayerNorm ----
    ln_kernel<<<BATCH * DT, 256>>>(fs + F_FC, q, ln_a, ln_b, out);

    (void)in_sizes; (void)n_in; (void)out_size;
}

// round 14
// speedup vs baseline: 1.1290x; 1.1290x over previous
#include <cuda_runtime.h>
#include <cuda_bf16.h>
#include <math.h>

typedef __nv_bfloat16 bf16;
typedef long long ll;

#define NHEAD  8
#define DMODEL 1024
#define DT     256
#define BATCH  32
#define LLEN   1024

// ---------------------------------------------------------------------------
// Static arenas. hi/lo bf16 twins share offsets.
// ---------------------------------------------------------------------------
#define O_QT   0LL            // (32, 1036, 256) padded transposed inputs
#define O_KT   8486912LL
#define O_VT   16973824LL
#define O_PRT  25460736LL     // (32, 1036, 256) proj output, transposed+padded
#define O_WCQ  33947648LL     // conv weights repacked (13, 256, 256)
#define O_WCK  34799616LL
#define O_WCV  35651584LL
#define O_WFC  36503552LL
#define O_WQT  37355520LL     // head weights transposed (8, 256, 1024)
#define O_WKT  39452672LL
#define O_WVT  41549824LL
#define O_PJW  43646976LL     // proj weight (1024, 2048) split only
#define O_QB   45744128LL     // conv outputs (32, 256, 1024)
#define O_KB   54132736LL
#define O_VB   62521344LL
#define O_QS   70909952LL     // (8, 32, 256, 256)
#define O_KS   87687168LL
#define O_VST  104464384LL    // vs transposed (8, 32, 256(d), 256(t))
#define O_ATT  121241600LL
#define O_CAT  138018816LL    // (32, 256, 2048)
#define BF_TOTAL 154796032LL

#define F_SC   0LL
#define F_FC   16777216LL
#define F_BIAS 25165824LL     // packed conv biases (3 x 256)
#define F_TOTAL 25166848LL

__device__ __align__(1024) bf16  g_bh[BF_TOTAL];
__device__ __align__(1024) bf16  g_bl[BF_TOTAL];
__device__ __align__(1024) float g_fs[F_TOTAL];

// ---------------------------------------------------------------------------
// helpers (plain sm_80+ PTX: cp.async, ldmatrix, mma.sync)
// ---------------------------------------------------------------------------
__device__ __forceinline__ unsigned smem_u32(const void* p) {
    unsigned a;
    asm("{ .reg .u64 t; cvta.to.shared.u64 t, %1; cvt.u32.u64 %0, t; }"
        : "=r"(a) : "l"(p));
    return a;
}
__device__ __forceinline__ void cp16(unsigned dst, const void* src) {
    asm volatile("cp.async.cg.shared.global [%0], [%1], 16;"
                 :: "r"(dst), "l"(src) : "memory");
}
__device__ __forceinline__ void cp_commit() {
    asm volatile("cp.async.commit_group;" ::: "memory");
}
template <int N>
__device__ __forceinline__ void cp_wait() {
    asm volatile("cp.async.wait_group %0;" :: "n"(N) : "memory");
}
__device__ __forceinline__ void ldsm4(unsigned r[4], unsigned addr) {
    asm volatile("ldmatrix.sync.aligned.m8n8.x4.shared.b16 {%0,%1,%2,%3}, [%4];"
                 : "=r"(r[0]), "=r"(r[1]), "=r"(r[2]), "=r"(r[3]) : "r"(addr));
}
__device__ __forceinline__ void mma16816(float* c, const unsigned a[4],
                                         unsigned b0, unsigned b1) {
    asm volatile(
        "mma.sync.aligned.m16n8k16.row.col.f32.bf16.bf16.f32 "
        "{%0,%1,%2,%3}, {%4,%5,%6,%7}, {%8,%9}, {%0,%1,%2,%3};"
        : "+f"(c[0]), "+f"(c[1]), "+f"(c[2]), "+f"(c[3])
        : "r"(a[0]), "r"(a[1]), "r"(a[2]), "r"(a[3]), "r"(b0), "r"(b1));
}
__device__ __forceinline__ void split2(float x, bf16& h, bf16& l) {
    h = __float2bfloat16(x);
    l = __float2bfloat16(x - __bfloat162float(h));
}

// ---------------------------------------------------------------------------
// Universal split-bf16 NT GEMM, taps + 3-level batching, 3-stage pipeline.
//   z = (z3*Z1 + z1)*Z2 + z2
//   C[m,n] = alpha * sum_t sum_k A[t][m,k] * B[t][n,k] + bias_m[z1*bias_z + m]
// CTA tile 128x128, K-chunk 32. smem rows 64B with XOR swizzle
// (chunk16 col c stored at c ^ ((row>>1)&3)) -> conflict-free ldmatrix/stores.
// Sub-tile 8KB, stage 32KB, 3 stages = 96KB; 2 CTAs/SM, 8 warps (4m x 2n).
// ---------------------------------------------------------------------------
#define SUBT  8192
#define STG   32768
#define GSMEM (3 * STG)

__global__ __launch_bounds__(256, 2)
void gemm_tc(
    const bf16* __restrict__ Ahi, const bf16* __restrict__ Alo,
    const bf16* __restrict__ Bhi, const bf16* __restrict__ Blo,
    float* __restrict__ Cf, bf16* __restrict__ Chi, bf16* __restrict__ Clo,
    int lda, int ldb, int ldc,
    ll a1, ll a2, ll b1, ll b2, ll c1, ll c2,
    ll a3, ll b3, ll c3,
    ll a_tap, ll b_tap, int kc_per_tap, int taps, int Z1, int Z2,
    float alpha, const float* __restrict__ bias_m, ll bias_z)
{
    extern __shared__ __align__(128) char smem[];
    const unsigned sb0 = smem_u32(smem);
    const int tid = threadIdx.x;
    const int warp = tid >> 5, lane = tid & 31;
    const int z = blockIdx.z;
    const int zz = Z1 * Z2;
    const int z3 = z / zz;
    const int rem = z - z3 * zz;
    const int z1 = rem / Z2, z2 = rem - z1 * Z2;
    const int m0 = blockIdx.y * 128, n0 = blockIdx.x * 128;

    const ll aoff = (ll)z3 * a3 + (ll)z1 * a1 + (ll)z2 * a2 + (ll)m0 * lda;
    const ll boff = (ll)z3 * b3 + (ll)z1 * b1 + (ll)z2 * b2 + (ll)n0 * ldb;
    const bf16* pAh = Ahi + aoff;
    const bf16* pAl = Alo + aoff;
    const bf16* pBh = Bhi + boff;
    const bf16* pBl = Blo + boff;

    // cp.async store indexing: row = tid>>2 (+64), logical 16B col = tid&3,
    // physical col = c ^ ((row>>1)&3)  (same xor for row and row+64).
    const int ld_row = tid >> 2;
    const int ld_c16 = tid & 3;
    const int xo = (ld_row >> 1) & 3;
    const unsigned ld_off0 = (unsigned)(ld_row * 64 + ((ld_c16 ^ xo) << 4));
    const unsigned ld_off1 = (unsigned)((ld_row + 64) * 64 + ((ld_c16 ^ xo) << 4));

    float acc[2][8][4];
#pragma unroll
    for (int a = 0; a < 2; a++)
#pragma unroll
        for (int b = 0; b < 8; b++)
#pragma unroll
            for (int c = 0; c < 4; c++) acc[a][b][c] = 0.f;

    const int NC = kc_per_tap * taps;

    auto issue = [&](int i) {
        const int t  = (taps == 1) ? 0 : (i / kc_per_tap);
        const int kc = i - t * kc_per_tap;
        const ll ao = (ll)t * a_tap + (ll)kc * 32 + (ll)ld_c16 * 8;
        const ll bo = (ll)t * b_tap + (ll)kc * 32 + (ll)ld_c16 * 8;
        const unsigned s = sb0 + (i % 3) * STG;
        const ll ar0 = (ll)ld_row * lda, ar1 = (ll)(ld_row + 64) * lda;
        const ll br0 = (ll)ld_row * ldb, br1 = (ll)(ld_row + 64) * ldb;
        cp16(s + ld_off0,             pAh + ao + ar0);
        cp16(s + ld_off1,             pAh + ao + ar1);
        cp16(s + SUBT + ld_off0,      pAl + ao + ar0);
        cp16(s + SUBT + ld_off1,      pAl + ao + ar1);
        cp16(s + 2 * SUBT + ld_off0,  pBh + bo + br0);
        cp16(s + 2 * SUBT + ld_off1,  pBh + bo + br1);
        cp16(s + 3 * SUBT + ld_off0,  pBl + bo + br0);
        cp16(s + 3 * SUBT + ld_off1,  pBl + bo + br1);
        cp_commit();
    };

    const int wm = (warp & 3) * 32;       // warp m origin
    const int wn = (warp >> 2) * 64;      // warp n origin
    const int li = lane & 7, lj = lane >> 3;
    // A fragment rows/cols (logical): row = wm + mb*16 + li + (lj&1)*8,
    // 16B-col = kk*2 + (lj>>1).  B: row = wn + nb*16 + li + (lj>>1)*8,
    // 16B-col = kk*2 + (lj&1).
    const int a_row_add = li + ((lj & 1) << 3);
    const int a_cadd    = lj >> 1;
    const int b_row_add = li + ((lj >> 1) << 3);
    const int b_cadd    = lj & 1;

    issue(0);
    if (NC > 1) issue(1);
    for (int i = 0; i < NC; i++) {
        if (i + 2 < NC)      { issue(i + 2); cp_wait<2>(); }
        else if (i + 1 < NC) { cp_wait<1>(); }
        else                 { cp_wait<0>(); }
        __syncthreads();

        const unsigned s = sb0 + (i % 3) * STG;
#pragma unroll
        for (int kk = 0; kk < 2; kk++) {
            unsigned ah[2][4], al[2][4];
#pragma unroll
            for (int mb = 0; mb < 2; mb++) {
                const int ar = wm + mb * 16 + a_row_add;
                const int ac = (kk * 2 + a_cadd) ^ ((ar >> 1) & 3);
                const unsigned aoffs = (unsigned)(ar * 64 + (ac << 4));
                ldsm4(ah[mb], s + aoffs);
                ldsm4(al[mb], s + SUBT + aoffs);
            }
#pragma unroll
            for (int nb = 0; nb < 4; nb++) {
                const int br = wn + nb * 16 + b_row_add;
                const int bc = (kk * 2 + b_cadd) ^ ((br >> 1) & 3);
                const unsigned boffs = (unsigned)(br * 64 + (bc << 4));
                unsigned bh[4], blr[4];
                ldsm4(bh,  s + 2 * SUBT + boffs);
                ldsm4(blr, s + 3 * SUBT + boffs);
#pragma unroll
                for (int mb = 0; mb < 2; mb++) {
#pragma unroll
                    for (int h = 0; h < 2; h++) {
                        float* c = acc[mb][nb * 2 + h];
                        mma16816(c, ah[mb], bh[2 * h],  bh[2 * h + 1]);
                        mma16816(c, ah[mb], blr[2 * h], blr[2 * h + 1]);
                        mma16816(c, al[mb], bh[2 * h],  bh[2 * h + 1]);
                    }
                }
            }
        }
        __syncthreads();
    }

    // ---- epilogue ----
    const ll coff = (ll)z3 * c3 + (ll)z1 * c1 + (ll)z2 * c2;
    const ll boffb = (ll)z1 * bias_z;
    const int g = lane >> 2, qd = lane & 3;
#pragma unroll
    for (int mb = 0; mb < 2; mb++) {
        const int r0 = m0 + wm + mb * 16 + g;
        const float bm0 = bias_m ? bias_m[boffb + r0] : 0.f;
        const float bm1 = bias_m ? bias_m[boffb + r0 + 8] : 0.f;
#pragma unroll
        for (int nf = 0; nf < 8; nf++) {
            const int col = n0 + wn + nf * 8 + qd * 2;
            const float* c = acc[mb][nf];
            float v00 = c[0] * alpha + bm0, v01 = c[1] * alpha + bm0;
            float v10 = c[2] * alpha + bm1, v11 = c[3] * alpha + bm1;
            const ll o0 = coff + (ll)r0 * ldc + col;
            const ll o1 = coff + (ll)(r0 + 8) * ldc + col;
            if (Cf) {
                *reinterpret_cast<float2*>(Cf + o0) = make_float2(v00, v01);
                *reinterpret_cast<float2*>(Cf + o1) = make_float2(v10, v11);
            }
            if (Chi) {
                bf16 h0, l0, h1, l1;
                split2(v00, h0, l0); split2(v01, h1, l1);
                *reinterpret_cast<__nv_bfloat162*>(Chi + o0) = __nv_bfloat162(h0, h1);
                *reinterpret_cast<__nv_bfloat162*>(Clo + o0) = __nv_bfloat162(l0, l1);
                split2(v10, h0, l0); split2(v11, h1, l1);
                *reinterpret_cast<__nv_bfloat162*>(Chi + o1) = __nv_bfloat162(h0, h1);
                *reinterpret_cast<__nv_bfloat162*>(Clo + o1) = __nv_bfloat162(l0, l1);
            }
        }
    }
}

// ---------------------------------------------------------------------------
// PREP A (launch #1): input transposes (z<96), weight transposes (96<=z<120),
// halo-pad zeroing + bias packing (z>=120). grid (32, 8, 127) x 256.
// ---------------------------------------------------------------------------
__global__ __launch_bounds__(256) void prep_a(
    const float* __restrict__ q, const float* __restrict__ k,
    const float* __restrict__ v,
    const float* __restrict__ wq, const float* __restrict__ wk,
    const float* __restrict__ wv,
    const float* __restrict__ b0, const float* __restrict__ b1,
    const float* __restrict__ b2,
    bf16* __restrict__ oh, bf16* __restrict__ ol, float* __restrict__ ob)
{
    const int zb = blockIdx.z;
    const int tx = threadIdx.x & 31, ty = threadIdx.x >> 5;
    __shared__ float t[32][33];

    if (zb < 96) {               // inputs: (32,256,1024) -> (32,1036,256)+6
        const int sel = zb >> 5, b = zb & 31;
        const float* in = (sel == 0 ? q : sel == 1 ? k : v) + (size_t)b * 262144;
        const size_t obase = (size_t)sel * 8486912 + (size_t)b * 265216;
        const int c0 = blockIdx.x * 32, r0 = blockIdx.y * 32;
#pragma unroll
        for (int j = 0; j < 4; j++)
            t[ty + 8 * j][tx] = in[(size_t)(r0 + ty + 8 * j) * 1024 + c0 + tx];
        __syncthreads();
#pragma unroll
        for (int j = 0; j < 4; j++) {
            float x = t[tx][ty + 8 * j];
            bf16 h, l; split2(x, h, l);
            size_t o = obase + (size_t)(c0 + ty + 8 * j + 6) * 256 + r0 + tx;
            (oh + O_QT)[o] = h; (ol + O_QT)[o] = l;
        }
    } else if (zb < 120) {       // head weights: (8,1024,256) -> (8,256,1024)
        const int zw = zb - 96;
        const int sel = zw >> 3, hh = zw & 7;
        const float* in = (sel == 0 ? wq : sel == 1 ? wk : wv) + (size_t)hh * 262144;
        const size_t obase = (size_t)sel * 2097152 + (size_t)hh * 262144;
        const int tlin = blockIdx.x * 8 + blockIdx.y;     // 0..255
        const int c0 = (tlin & 7) * 32, r0 = (tlin >> 3) * 32;
#pragma unroll
        for (int j = 0; j < 4; j++)
            t[ty + 8 * j][tx] = in[(size_t)(r0 + ty + 8 * j) * 256 + c0 + tx];
        __syncthreads();
#pragma unroll
        for (int j = 0; j < 4; j++) {
            float x = t[tx][ty + 8 * j];
            bf16 h, l; split2(x, h, l);
            size_t o = obase + (size_t)(c0 + ty + 8 * j) * 1024 + r0 + tx;
            (oh + O_WQT)[o] = h; (ol + O_WQT)[o] = l;
        }
    } else {                      // pads + bias, 1D
        const int blin = blockIdx.y * 32 + blockIdx.x;    // 0..255
        const int idx = ((zb - 120) * 256 + blin) * 256 + threadIdx.x;
        if (idx < 393216) {
            int b = idx / 3072, rem2 = idx % 3072;
            int r12 = rem2 >> 8, c = rem2 & 255;
            int row = (r12 < 6) ? r12 : (1024 + r12);
            size_t o = (size_t)b * 265216 + (size_t)row * 256 + c;
            (oh + O_QT)[o] = __float2bfloat16(0.f);
            (ol + O_QT)[o] = __float2bfloat16(0.f);
        } else if (idx < 393984) {
            int i = idx - 393216;
            int sel = i >> 8, c = i & 255;
            ob[i] = (sel == 0 ? b0 : sel == 1 ? b1 : b2)[c];
        }
    }
}

// ---------------------------------------------------------------------------
// PREP B (launch #2): conv-weight repack (4 tensors) + proj-weight split.
// grid 21504 x 256.
// ---------------------------------------------------------------------------
__global__ __launch_bounds__(256) void prep_b(
    const float* __restrict__ w0, const float* __restrict__ w1,
    const float* __restrict__ w2, const float* __restrict__ w3,
    const float* __restrict__ pw,
    bf16* __restrict__ oh, bf16* __restrict__ ol)
{
    int idx = blockIdx.x * 256 + threadIdx.x;
    if (idx < 3407872) {
        int sel = idx / 851968, r = idx - sel * 851968;
        int t = r >> 16, rem = r & 65535;
        int o = rem >> 8, c = rem & 255;
        const float* w = sel == 0 ? w0 : sel == 1 ? w1 : sel == 2 ? w2 : w3;
        float x = w[(size_t)(o * 256 + c) * 13 + t];
        bf16 h, l; split2(x, h, l);
        (oh + O_WCQ)[idx] = h; (ol + O_WCQ)[idx] = l;
    } else {
        int i = idx - 3407872;
        if (i < 2097152) {
            bf16 h, l; split2(pw[i], h, l);
            (oh + O_PJW)[i] = h; (ol + O_PJW)[i] = l;
        }
    }
}

// ---------------------------------------------------------------------------
// softmax over last axis (256); fp32 attn to d_out AND split pair to arena.
// ---------------------------------------------------------------------------
__global__ __launch_bounds__(256) void softmax_split(
    const float* __restrict__ scores, float* __restrict__ attn,
    bf16* __restrict__ ah, bf16* __restrict__ al)
{
    const int row  = blockIdx.x * 8 + (threadIdx.x >> 5);
    const int lane = threadIdx.x & 31;
    const float* s = scores + (size_t)row * 256;

    float v[8];
    float mx = -1e30f;
#pragma unroll
    for (int j = 0; j < 8; j++) { v[j] = s[lane + 32 * j]; mx = fmaxf(mx, v[j]); }
#pragma unroll
    for (int o = 16; o; o >>= 1) mx = fmaxf(mx, __shfl_xor_sync(0xffffffffu, mx, o));
    float sum = 0.f;
#pragma unroll
    for (int j = 0; j < 8; j++) { v[j] = expf(v[j] - mx); sum += v[j]; }
#pragma unroll
    for (int o = 16; o; o >>= 1) sum += __shfl_xor_sync(0xffffffffu, sum, o);
    const float inv = 1.f / sum;

    float* a  = attn + (size_t)row * 256;
    bf16* hh = ah + (size_t)row * 256;
    bf16* ll_ = al + (size_t)row * 256;
#pragma unroll
    for (int j = 0; j < 8; j++) {
        float p = v[j] * inv;
        a[lane + 32 * j] = p;
        bf16 h, l; split2(p, h, l);
        hh[lane + 32 * j] = h; ll_[lane + 32 * j] = l;
    }
}

// ---------------------------------------------------------------------------
// residual + LayerNorm (ddof=1, eps added to sigma)
// ---------------------------------------------------------------------------
__global__ __launch_bounds__(256) void ln_kernel(
    const float* __restrict__ fc, const float* __restrict__ q,
    const float* __restrict__ ga, const float* __restrict__ gb,
    float* __restrict__ out)
{
    const int row = blockIdx.x;
    const float* f  = fc + (size_t)row * DMODEL;
    const float* qq = q  + (size_t)row * DMODEL;
    const int tid = threadIdx.x;

    float zv[4];
    float s = 0.f, ss = 0.f;
#pragma unroll
    for (int j = 0; j < 4; j++) {
        float zz = f[tid + 256 * j] + qq[tid + 256 * j];
        zv[j] = zz; s += zz; ss += zz * zz;
    }
    __shared__ float rs[8], rss[8];
#pragma unroll
    for (int o = 16; o; o >>= 1) {
        s  += __shfl_xor_sync(0xffffffffu, s, o);
        ss += __shfl_xor_sync(0xffffffffu, ss, o);
    }
    if ((tid & 31) == 0) { rs[tid >> 5] = s; rss[tid >> 5] = ss; }
    __syncthreads();
    if (tid < 32) {
        float a = (tid < 8) ? rs[tid] : 0.f;
        float b = (tid < 8) ? rss[tid] : 0.f;
#pragma unroll
        for (int o = 4; o; o >>= 1) {
            a += __shfl_xor_sync(0xffffffffu, a, o);
            b += __shfl_xor_sync(0xffffffffu, b, o);
        }
        if (tid == 0) { rs[0] = a; rss[0] = b; }
    }
    __syncthreads();
    const float mu  = rs[0] * (1.f / DMODEL);
    const float var = (rss[0] - (float)DMODEL * mu * mu) * (1.f / (DMODEL - 1));
    const float inv = 1.f / (sqrtf(fmaxf(var, 0.f)) + 1e-3f);
    float* o_ = out + (size_t)row * DMODEL;
#pragma unroll
    for (int j = 0; j < 4; j++) {
        const int col = tid + 256 * j;
        o_[col] = (zv[j] - mu) * inv * ga[col] + gb[col];
    }
}

// ---------------------------------------------------------------------------
extern "C" void kernel_launch(void* const* d_in, const int* in_sizes, int n_in,
                              void* d_out, int out_size)
{
    const float* q    = (const float*)d_in[0];
    const float* k    = (const float*)d_in[1];
    const float* v    = (const float*)d_in[2];
    const float* cq_w = (const float*)d_in[3];
    const float* cq_b = (const float*)d_in[4];
    const float* ck_w = (const float*)d_in[5];
    const float* ck_b = (const float*)d_in[6];
    const float* cv_w = (const float*)d_in[7];
    const float* cv_b = (const float*)d_in[8];
    const float* w_qs = (const float*)d_in[9];
    const float* w_ks = (const float*)d_in[10];
    const float* w_vs = (const float*)d_in[11];
    const float* pj_w = (const float*)d_in[12];
    const float* pj_b = (const float*)d_in[13];
    const float* fc_w = (const float*)d_in[14];
    const float* fc_b = (const float*)d_in[15];
    const float* ln_a = (const float*)d_in[16];
    const float* ln_b = (const float*)d_in[17];

    bf16 *bh = nullptr, *bl = nullptr; float* fs = nullptr;
    cudaGetSymbolAddress((void**)&bh, g_bh);
    cudaGetSymbolAddress((void**)&bl, g_bl);
    cudaGetSymbolAddress((void**)&fs, g_fs);

    cudaFuncSetAttribute(gemm_tc, cudaFuncAttributeMaxDynamicSharedMemorySize, GSMEM);

    float* out  = (float*)d_out;
    float* attn = out + (size_t)BATCH * DT * LLEN;

    // ---- preps: exactly 2 launches; all subsequent launches are GEMMs ----
    prep_a<<<dim3(32, 8, 127), 256>>>(q, k, v, w_qs, w_ks, w_vs,
                                      cq_b, ck_b, cv_b, bh, bl, fs + F_BIAS); // 1
    prep_b<<<21504, 256>>>(cq_w, ck_w, cv_w, fc_w, pj_w, bh, bl);             // 2

    // ---- 3. conv q/k/v MERGED: z1 = conv idx (0..2), z2 = batch ----
    gemm_tc<<<dim3(8, 2, 96), 256, GSMEM>>>(
        bh + O_WCQ, bl + O_WCQ, bh + O_QT, bl + O_QT,
        nullptr, bh + O_QB, bl + O_QB, 256, 256, 1024,
        851968, 0, 8486912, 265216, 8388608, 262144,
        0, 0, 0,
        65536, 256, 8, 13, 3, 32, 1.f, fs + F_BIAS, 256);

    // ---- 4. Q + K head projections MERGED: z3 = {q,k}, z1 = h, z2 = b ----
    gemm_tc<<<dim3(2, 2, 512), 256, GSMEM>>>(
        bh + O_QB, bl + O_QB, bh + O_WQT, bl + O_WQT,
        nullptr, bh + O_QS, bl + O_QS, 1024, 1024, 256,
        0, 262144, 262144, 0, 2097152, 65536,
        8388608, 2097152, 16777216,
        0, 0, 32, 1, 8, 32, 1.f, nullptr, 0);

    // ---- 5. V head projection, transposed output ----
    gemm_tc<<<dim3(2, 2, 256), 256, GSMEM>>>(
        bh + O_WVT, bl + O_WVT, bh + O_VB, bl + O_VB,
        nullptr, bh + O_VST, bl + O_VST, 1024, 1024, 256,
        262144, 0, 0, 262144, 2097152, 65536,
        0, 0, 0,
        0, 0, 32, 1, 8, 32, 1.f, nullptr, 0);

    // ---- 6. scores = qs . ks^T / 32 -> fp32 ----
    gemm_tc<<<dim3(2, 2, 256), 256, GSMEM>>>(
        bh + O_QS, bl + O_QS, bh + O_KS, bl + O_KS,
        fs + F_SC, nullptr, nullptr, 256, 256, 256,
        2097152, 65536, 2097152, 65536, 2097152, 65536,
        0, 0, 0,
        0, 0, 8, 1, 8, 32, 1.f / 32.f, nullptr, 0);

    // ---- 7. softmax -> attns (d_out) + split arena ----
    softmax_split<<<8192, 256>>>(fs + F_SC, attn, bh + O_ATT, bl + O_ATT);

    // ---- 8. out = attn . vsT^T -> cat (B, 256, 2048) ----
    gemm_tc<<<dim3(2, 2, 256), 256, GSMEM>>>(
        bh + O_ATT, bl + O_ATT, bh + O_VST, bl + O_VST,
        nullptr, bh + O_CAT, bl + O_CAT, 256, 256, 2048,
        2097152, 65536, 2097152, 65536, 256, 524288,
        0, 0, 0,
        0, 0, 8, 1, 8, 32, 1.f, nullptr, 0);

    // ---- 9. proj, transposed: C[dm][t] -> prT (pad row offset 6) ----
    gemm_tc<<<dim3(2, 8, 32), 256, GSMEM>>>(
        bh + O_PJW, bl + O_PJW, bh + O_CAT, bl + O_CAT,
        nullptr, bh + O_PRT + 1536, bl + O_PRT + 1536, 2048, 2048, 256,
        0, 0, 0, 524288, 0, 265216,
        0, 0, 0,
        0, 0, 64, 1, 1, 32, 1.f, pj_b, 0);

    // ---- 10. fc conv: M=256(o), N=1024(l), K=256 x 13 -> fp32 ----
    gemm_tc<<<dim3(8, 2, 32), 256, GSMEM>>>(
        bh + O_WFC, bl + O_WFC, bh + O_PRT, bl + O_PRT,
        fs + F_FC, nullptr, nullptr, 256, 256, 1024,
        0, 0, 0, 265216, 0, 262144,
        0, 0, 0,
        65536, 256, 8, 13, 1, 32, 1.f, fc_b, 0);

    // ---- 11. residual + LayerNorm ----
    ln_kernel<<<BATCH * DT, 256>>>(fs + F_FC, q, ln_a, ln_b, out);

    (void)in_sizes; (void)n_in; (void)out_size;
}

// round 15
// speedup vs baseline: 1.1306x; 1.0014x over previous
#include <cuda_runtime.h>
#include <cuda_bf16.h>
#include <math.h>

typedef __nv_bfloat16 bf16;
typedef long long ll;

#define NHEAD  8
#define DMODEL 1024
#define DT     256
#define BATCH  32
#define LLEN   1024

// ---------------------------------------------------------------------------
// Static arenas. hi/lo bf16 twins share offsets.
// ---------------------------------------------------------------------------
#define O_QT   0LL            // (32, 1036, 256) padded transposed inputs
#define O_KT   8486912LL
#define O_VT   16973824LL
#define O_PRT  25460736LL     // (32, 1036, 256) proj output, transposed+padded
#define O_WCQ  33947648LL     // conv weights repacked (13, 256, 256)
#define O_WCK  34799616LL
#define O_WCV  35651584LL
#define O_WFC  36503552LL
#define O_WQT  37355520LL     // head weights transposed (8, 256, 1024)
#define O_WKT  39452672LL
#define O_WVT  41549824LL
#define O_PJW  43646976LL     // proj weight (1024, 2048) split only
#define O_QB   45744128LL     // conv outputs (32, 256, 1024)
#define O_KB   54132736LL
#define O_VB   62521344LL
#define O_QS   70909952LL     // (8, 32, 256, 256)
#define O_KS   87687168LL
#define O_VST  104464384LL    // vs transposed (8, 32, 256(d), 256(t))
#define O_ATT  121241600LL
#define O_CAT  138018816LL    // (32, 256, 2048)
#define BF_TOTAL 154796032LL

#define F_SC   0LL
#define F_FC   16777216LL
#define F_BIAS 25165824LL     // packed conv biases (3 x 256)
#define F_TOTAL 25166848LL

__device__ __align__(1024) bf16  g_bh[BF_TOTAL];
__device__ __align__(1024) bf16  g_bl[BF_TOTAL];
__device__ __align__(1024) float g_fs[F_TOTAL];

// ---------------------------------------------------------------------------
// helpers (plain sm_80+ PTX: cp.async, ldmatrix, mma.sync)
// ---------------------------------------------------------------------------
__device__ __forceinline__ unsigned smem_u32(const void* p) {
    unsigned a;
    asm("{ .reg .u64 t; cvta.to.shared.u64 t, %1; cvt.u32.u64 %0, t; }"
        : "=r"(a) : "l"(p));
    return a;
}
__device__ __forceinline__ void cp16(unsigned dst, const void* src) {
    asm volatile("cp.async.cg.shared.global [%0], [%1], 16;"
                 :: "r"(dst), "l"(src) : "memory");
}
__device__ __forceinline__ void cp_commit() {
    asm volatile("cp.async.commit_group;" ::: "memory");
}
template <int N>
__device__ __forceinline__ void cp_wait() {
    asm volatile("cp.async.wait_group %0;" :: "n"(N) : "memory");
}
__device__ __forceinline__ void ldsm4(unsigned r[4], unsigned addr) {
    asm volatile("ldmatrix.sync.aligned.m8n8.x4.shared.b16 {%0,%1,%2,%3}, [%4];"
                 : "=r"(r[0]), "=r"(r[1]), "=r"(r[2]), "=r"(r[3]) : "r"(addr));
}
__device__ __forceinline__ void mma16816(float* c, const unsigned a[4],
                                         unsigned b0, unsigned b1) {
    asm volatile(
        "mma.sync.aligned.m16n8k16.row.col.f32.bf16.bf16.f32 "
        "{%0,%1,%2,%3}, {%4,%5,%6,%7}, {%8,%9}, {%0,%1,%2,%3};"
        : "+f"(c[0]), "+f"(c[1]), "+f"(c[2]), "+f"(c[3])
        : "r"(a[0]), "r"(a[1]), "r"(a[2]), "r"(a[3]), "r"(b0), "r"(b1));
}
__device__ __forceinline__ void split2(float x, bf16& h, bf16& l) {
    h = __float2bfloat16(x);
    l = __float2bfloat16(x - __bfloat162float(h));
}

// ---------------------------------------------------------------------------
// Universal split-bf16 NT GEMM, taps + 3-level batching, 3-stage pipeline.
//   z = (z3*Z1 + z1)*Z2 + z2
//   C[m,n] = alpha * sum_t sum_k A[t][m,k] * B[t][n,k] + bias_m[z1*bias_z + m]
// CTA tile 128x128, K-chunk 32. smem rows 64B with XOR swizzle
// (chunk16 col c stored at c ^ ((row>>1)&3)) -> conflict-free ldmatrix/stores.
// Sub-tile 8KB, stage 32KB, 3 stages = 96KB; 2 CTAs/SM, 8 warps (4m x 2n).
// ---------------------------------------------------------------------------
#define SUBT  8192
#define STG   32768
#define GSMEM (3 * STG)

__global__ __launch_bounds__(256, 2)
void gemm_tc(
    const bf16* __restrict__ Ahi, const bf16* __restrict__ Alo,
    const bf16* __restrict__ Bhi, const bf16* __restrict__ Blo,
    float* __restrict__ Cf, bf16* __restrict__ Chi, bf16* __restrict__ Clo,
    int lda, int ldb, int ldc,
    ll a1, ll a2, ll b1, ll b2, ll c1, ll c2,
    ll a3, ll b3, ll c3,
    ll a_tap, ll b_tap, int kc_per_tap, int taps, int Z1, int Z2,
    float alpha, const float* __restrict__ bias_m, ll bias_z)
{
    extern __shared__ __align__(128) char smem[];
    const unsigned sb0 = smem_u32(smem);
    const int tid = threadIdx.x;
    const int warp = tid >> 5, lane = tid & 31;
    const int z = blockIdx.z;
    const int zz = Z1 * Z2;
    const int z3 = z / zz;
    const int rem = z - z3 * zz;
    const int z1 = rem / Z2, z2 = rem - z1 * Z2;
    const int m0 = blockIdx.y * 128, n0 = blockIdx.x * 128;

    const ll aoff = (ll)z3 * a3 + (ll)z1 * a1 + (ll)z2 * a2 + (ll)m0 * lda;
    const ll boff = (ll)z3 * b3 + (ll)z1 * b1 + (ll)z2 * b2 + (ll)n0 * ldb;
    const bf16* pAh = Ahi + aoff;
    const bf16* pAl = Alo + aoff;
    const bf16* pBh = Bhi + boff;
    const bf16* pBl = Blo + boff;

    // cp.async store indexing: row = tid>>2 (+64), logical 16B col = tid&3,
    // physical col = c ^ ((row>>1)&3)  (same xor for row and row+64).
    const int ld_row = tid >> 2;
    const int ld_c16 = tid & 3;
    const int xo = (ld_row >> 1) & 3;
    const unsigned ld_off0 = (unsigned)(ld_row * 64 + ((ld_c16 ^ xo) << 4));
    const unsigned ld_off1 = (unsigned)((ld_row + 64) * 64 + ((ld_c16 ^ xo) << 4));

    float acc[2][8][4];
#pragma unroll
    for (int a = 0; a < 2; a++)
#pragma unroll
        for (int b = 0; b < 8; b++)
#pragma unroll
            for (int c = 0; c < 4; c++) acc[a][b][c] = 0.f;

    const int NC = kc_per_tap * taps;

    auto issue = [&](int i) {
        const int t  = (taps == 1) ? 0 : (i / kc_per_tap);
        const int kc = i - t * kc_per_tap;
        const ll ao = (ll)t * a_tap + (ll)kc * 32 + (ll)ld_c16 * 8;
        const ll bo = (ll)t * b_tap + (ll)kc * 32 + (ll)ld_c16 * 8;
        const unsigned s = sb0 + (i % 3) * STG;
        const ll ar0 = (ll)ld_row * lda, ar1 = (ll)(ld_row + 64) * lda;
        const ll br0 = (ll)ld_row * ldb, br1 = (ll)(ld_row + 64) * ldb;
        cp16(s + ld_off0,             pAh + ao + ar0);
        cp16(s + ld_off1,             pAh + ao + ar1);
        cp16(s + SUBT + ld_off0,      pAl + ao + ar0);
        cp16(s + SUBT + ld_off1,      pAl + ao + ar1);
        cp16(s + 2 * SUBT + ld_off0,  pBh + bo + br0);
        cp16(s + 2 * SUBT + ld_off1,  pBh + bo + br1);
        cp16(s + 3 * SUBT + ld_off0,  pBl + bo + br0);
        cp16(s + 3 * SUBT + ld_off1,  pBl + bo + br1);
        cp_commit();
    };

    const int wm = (warp & 3) * 32;       // warp m origin
    const int wn = (warp >> 2) * 64;      // warp n origin
    const int li = lane & 7, lj = lane >> 3;
    // A fragment rows/cols (logical): row = wm + mb*16 + li + (lj&1)*8,
    // 16B-col = kk*2 + (lj>>1).  B: row = wn + nb*16 + li + (lj>>1)*8,
    // 16B-col = kk*2 + (lj&1).
    const int a_row_add = li + ((lj & 1) << 3);
    const int a_cadd    = lj >> 1;
    const int b_row_add = li + ((lj >> 1) << 3);
    const int b_cadd    = lj & 1;

    issue(0);
    if (NC > 1) issue(1);
    for (int i = 0; i < NC; i++) {
        if (i + 2 < NC)      { issue(i + 2); cp_wait<2>(); }
        else if (i + 1 < NC) { cp_wait<1>(); }
        else                 { cp_wait<0>(); }
        __syncthreads();

        const unsigned s = sb0 + (i % 3) * STG;
#pragma unroll
        for (int kk = 0; kk < 2; kk++) {
            unsigned ah[2][4], al[2][4];
#pragma unroll
            for (int mb = 0; mb < 2; mb++) {
                const int ar = wm + mb * 16 + a_row_add;
                const int ac = (kk * 2 + a_cadd) ^ ((ar >> 1) & 3);
                const unsigned aoffs = (unsigned)(ar * 64 + (ac << 4));
                ldsm4(ah[mb], s + aoffs);
                ldsm4(al[mb], s + SUBT + aoffs);
            }
#pragma unroll
            for (int nb = 0; nb < 4; nb++) {
                const int br = wn + nb * 16 + b_row_add;
                const int bc = (kk * 2 + b_cadd) ^ ((br >> 1) & 3);
                const unsigned boffs = (unsigned)(br * 64 + (bc << 4));
                unsigned bh[4], blr[4];
                ldsm4(bh,  s + 2 * SUBT + boffs);
                ldsm4(blr, s + 3 * SUBT + boffs);
#pragma unroll
                for (int mb = 0; mb < 2; mb++) {
#pragma unroll
                    for (int h = 0; h < 2; h++) {
                        float* c = acc[mb][nb * 2 + h];
                        mma16816(c, ah[mb], bh[2 * h],  bh[2 * h + 1]);
                        mma16816(c, ah[mb], blr[2 * h], blr[2 * h + 1]);
                        mma16816(c, al[mb], bh[2 * h],  bh[2 * h + 1]);
                    }
                }
            }
        }
        __syncthreads();
    }

    // ---- epilogue ----
    const ll coff = (ll)z3 * c3 + (ll)z1 * c1 + (ll)z2 * c2;
    const ll boffb = (ll)z1 * bias_z;
    const int g = lane >> 2, qd = lane & 3;
#pragma unroll
    for (int mb = 0; mb < 2; mb++) {
        const int r0 = m0 + wm + mb * 16 + g;
        const float bm0 = bias_m ? bias_m[boffb + r0] : 0.f;
        const float bm1 = bias_m ? bias_m[boffb + r0 + 8] : 0.f;
#pragma unroll
        for (int nf = 0; nf < 8; nf++) {
            const int col = n0 + wn + nf * 8 + qd * 2;
            const float* c = acc[mb][nf];
            float v00 = c[0] * alpha + bm0, v01 = c[1] * alpha + bm0;
            float v10 = c[2] * alpha + bm1, v11 = c[3] * alpha + bm1;
            const ll o0 = coff + (ll)r0 * ldc + col;
            const ll o1 = coff + (ll)(r0 + 8) * ldc + col;
            if (Cf) {
                *reinterpret_cast<float2*>(Cf + o0) = make_float2(v00, v01);
                *reinterpret_cast<float2*>(Cf + o1) = make_float2(v10, v11);
            }
            if (Chi) {
                bf16 h0, l0, h1, l1;
                split2(v00, h0, l0); split2(v01, h1, l1);
                *reinterpret_cast<__nv_bfloat162*>(Chi + o0) = __nv_bfloat162(h0, h1);
                *reinterpret_cast<__nv_bfloat162*>(Clo + o0) = __nv_bfloat162(l0, l1);
                split2(v10, h0, l0); split2(v11, h1, l1);
                *reinterpret_cast<__nv_bfloat162*>(Chi + o1) = __nv_bfloat162(h0, h1);
                *reinterpret_cast<__nv_bfloat162*>(Clo + o1) = __nv_bfloat162(l0, l1);
            }
        }
    }
}

// ---------------------------------------------------------------------------
// PREP A (launch #1): input transposes (z<96), weight transposes (96<=z<120),
// halo-pad zeroing + bias packing (z>=120). grid (32, 8, 127) x 256.
// ---------------------------------------------------------------------------
__global__ __launch_bounds__(256) void prep_a(
    const float* __restrict__ q, const float* __restrict__ k,
    const float* __restrict__ v,
    const float* __restrict__ wq, const float* __restrict__ wk,
    const float* __restrict__ wv,
    const float* __restrict__ b0, const float* __restrict__ b1,
    const float* __restrict__ b2,
    bf16* __restrict__ oh, bf16* __restrict__ ol, float* __restrict__ ob)
{
    const int zb = blockIdx.z;
    const int tx = threadIdx.x & 31, ty = threadIdx.x >> 5;
    __shared__ float t[32][33];

    if (zb < 96) {               // inputs: (32,256,1024) -> (32,1036,256)+6
        const int sel = zb >> 5, b = zb & 31;
        const float* in = (sel == 0 ? q : sel == 1 ? k : v) + (size_t)b * 262144;
        const size_t obase = (size_t)sel * 8486912 + (size_t)b * 265216;
        const int c0 = blockIdx.x * 32, r0 = blockIdx.y * 32;
#pragma unroll
        for (int j = 0; j < 4; j++)
            t[ty + 8 * j][tx] = in[(size_t)(r0 + ty + 8 * j) * 1024 + c0 + tx];
        __syncthreads();
#pragma unroll
        for (int j = 0; j < 4; j++) {
            float x = t[tx][ty + 8 * j];
            bf16 h, l; split2(x, h, l);
            size_t o = obase + (size_t)(c0 + ty + 8 * j + 6) * 256 + r0 + tx;
            (oh + O_QT)[o] = h; (ol + O_QT)[o] = l;
        }
    } else if (zb < 120) {       // head weights: (8,1024,256) -> (8,256,1024)
        const int zw = zb - 96;
        const int sel = zw >> 3, hh = zw & 7;
        const float* in = (sel == 0 ? wq : sel == 1 ? wk : wv) + (size_t)hh * 262144;
        const size_t obase = (size_t)sel * 2097152 + (size_t)hh * 262144;
        const int tlin = blockIdx.x * 8 + blockIdx.y;     // 0..255
        const int c0 = (tlin & 7) * 32, r0 = (tlin >> 3) * 32;
#pragma unroll
        for (int j = 0; j < 4; j++)
            t[ty + 8 * j][tx] = in[(size_t)(r0 + ty + 8 * j) * 256 + c0 + tx];
        __syncthreads();
#pragma unroll
        for (int j = 0; j < 4; j++) {
            float x = t[tx][ty + 8 * j];
            bf16 h, l; split2(x, h, l);
            size_t o = obase + (size_t)(c0 + ty + 8 * j) * 1024 + r0 + tx;
            (oh + O_WQT)[o] = h; (ol + O_WQT)[o] = l;
        }
    } else {                      // pads + bias, 1D
        const int blin = blockIdx.y * 32 + blockIdx.x;    // 0..255
        const int idx = ((zb - 120) * 256 + blin) * 256 + threadIdx.x;
        if (idx < 393216) {
            int b = idx / 3072, rem2 = idx % 3072;
            int r12 = rem2 >> 8, c = rem2 & 255;
            int row = (r12 < 6) ? r12 : (1024 + r12);
            size_t o = (size_t)b * 265216 + (size_t)row * 256 + c;
            (oh + O_QT)[o] = __float2bfloat16(0.f);
            (ol + O_QT)[o] = __float2bfloat16(0.f);
        } else if (idx < 393984) {
            int i = idx - 393216;
            int sel = i >> 8, c = i & 255;
            ob[i] = (sel == 0 ? b0 : sel == 1 ? b1 : b2)[c];
        }
    }
}

// ---------------------------------------------------------------------------
// PREP B (launch #2): conv-weight repack (4 tensors) + proj-weight split.
// grid 21504 x 256.
// ---------------------------------------------------------------------------
__global__ __launch_bounds__(256) void prep_b(
    const float* __restrict__ w0, const float* __restrict__ w1,
    const float* __restrict__ w2, const float* __restrict__ w3,
    const float* __restrict__ pw,
    bf16* __restrict__ oh, bf16* __restrict__ ol)
{
    int idx = blockIdx.x * 256 + threadIdx.x;
    if (idx < 3407872) {
        int sel = idx / 851968, r = idx - sel * 851968;
        int t = r >> 16, rem = r & 65535;
        int o = rem >> 8, c = rem & 255;
        const float* w = sel == 0 ? w0 : sel == 1 ? w1 : sel == 2 ? w2 : w3;
        float x = w[(size_t)(o * 256 + c) * 13 + t];
        bf16 h, l; split2(x, h, l);
        (oh + O_WCQ)[idx] = h; (ol + O_WCQ)[idx] = l;
    } else {
        int i = idx - 3407872;
        if (i < 2097152) {
            bf16 h, l; split2(pw[i], h, l);
            (oh + O_PJW)[i] = h; (ol + O_PJW)[i] = l;
        }
    }
}

// ---------------------------------------------------------------------------
// softmax over last axis (256); fp32 attn to d_out AND split pair to arena.
// ---------------------------------------------------------------------------
__global__ __launch_bounds__(256) void softmax_split(
    const float* __restrict__ scores, float* __restrict__ attn,
    bf16* __restrict__ ah, bf16* __restrict__ al)
{
    const int row  = blockIdx.x * 8 + (threadIdx.x >> 5);
    const int lane = threadIdx.x & 31;
    const float* s = scores + (size_t)row * 256;

    float v[8];
    float mx = -1e30f;
#pragma unroll
    for (int j = 0; j < 8; j++) { v[j] = s[lane + 32 * j]; mx = fmaxf(mx, v[j]); }
#pragma unroll
    for (int o = 16; o; o >>= 1) mx = fmaxf(mx, __shfl_xor_sync(0xffffffffu, mx, o));
    float sum = 0.f;
#pragma unroll
    for (int j = 0; j < 8; j++) { v[j] = expf(v[j] - mx); sum += v[j]; }
#pragma unroll
    for (int o = 16; o; o >>= 1) sum += __shfl_xor_sync(0xffffffffu, sum, o);
    const float inv = 1.f / sum;

    float* a  = attn + (size_t)row * 256;
    bf16* hh = ah + (size_t)row * 256;
    bf16* ll_ = al + (size_t)row * 256;
#pragma unroll
    for (int j = 0; j < 8; j++) {
        float p = v[j] * inv;
        a[lane + 32 * j] = p;
        bf16 h, l; split2(p, h, l);
        hh[lane + 32 * j] = h; ll_[lane + 32 * j] = l;
    }
}

// ---------------------------------------------------------------------------
// residual + LayerNorm (ddof=1, eps added to sigma)
// ---------------------------------------------------------------------------
__global__ __launch_bounds__(256) void ln_kernel(
    const float* __restrict__ fc, const float* __restrict__ q,
    const float* __restrict__ ga, const float* __restrict__ gb,
    float* __restrict__ out)
{
    const int row = blockIdx.x;
    const float* f  = fc + (size_t)row * DMODEL;
    const float* qq = q  + (size_t)row * DMODEL;
    const int tid = threadIdx.x;

    float zv[4];
    float s = 0.f, ss = 0.f;
#pragma unroll
    for (int j = 0; j < 4; j++) {
        float zz = f[tid + 256 * j] + qq[tid + 256 * j];
        zv[j] = zz; s += zz; ss += zz * zz;
    }
    __shared__ float rs[8], rss[8];
#pragma unroll
    for (int o = 16; o; o >>= 1) {
        s  += __shfl_xor_sync(0xffffffffu, s, o);
        ss += __shfl_xor_sync(0xffffffffu, ss, o);
    }
    if ((tid & 31) == 0) { rs[tid >> 5] = s; rss[tid >> 5] = ss; }
    __syncthreads();
    if (tid < 32) {
        float a = (tid < 8) ? rs[tid] : 0.f;
        float b = (tid < 8) ? rss[tid] : 0.f;
#pragma unroll
        for (int o = 4; o; o >>= 1) {
            a += __shfl_xor_sync(0xffffffffu, a, o);
            b += __shfl_xor_sync(0xffffffffu, b, o);
        }
        if (tid == 0) { rs[0] = a; rss[0] = b; }
    }
    __syncthreads();
    const float mu  = rs[0] * (1.f / DMODEL);
    const float var = (rss[0] - (float)DMODEL * mu * mu) * (1.f / (DMODEL - 1));
    const float inv = 1.f / (sqrtf(fmaxf(var, 0.f)) + 1e-3f);
    float* o_ = out + (size_t)row * DMODEL;
#pragma unroll
    for (int j = 0; j < 4; j++) {
        const int col = tid + 256 * j;
        o_[col] = (zv[j] - mu) * inv * ga[col] + gb[col];
    }
}

// ---------------------------------------------------------------------------
extern "C" void kernel_launch(void* const* d_in, const int* in_sizes, int n_in,
                              void* d_out, int out_size)
{
    const float* q    = (const float*)d_in[0];
    const float* k    = (const float*)d_in[1];
    const float* v    = (const float*)d_in[2];
    const float* cq_w = (const float*)d_in[3];
    const float* cq_b = (const float*)d_in[4];
    const float* ck_w = (const float*)d_in[5];
    const float* ck_b = (const float*)d_in[6];
    const float* cv_w = (const float*)d_in[7];
    const float* cv_b = (const float*)d_in[8];
    const float* w_qs = (const float*)d_in[9];
    const float* w_ks = (const float*)d_in[10];
    const float* w_vs = (const float*)d_in[11];
    const float* pj_w = (const float*)d_in[12];
    const float* pj_b = (const float*)d_in[13];
    const float* fc_w = (const float*)d_in[14];
    const float* fc_b = (const float*)d_in[15];
    const float* ln_a = (const float*)d_in[16];
    const float* ln_b = (const float*)d_in[17];

    bf16 *bh = nullptr, *bl = nullptr; float* fs = nullptr;
    cudaGetSymbolAddress((void**)&bh, g_bh);
    cudaGetSymbolAddress((void**)&bl, g_bl);
    cudaGetSymbolAddress((void**)&fs, g_fs);

    cudaFuncSetAttribute(gemm_tc, cudaFuncAttributeMaxDynamicSharedMemorySize, GSMEM);

    float* out  = (float*)d_out;
    float* attn = out + (size_t)BATCH * DT * LLEN;

    // ---- preps: exactly 2 launches; all subsequent launches are GEMMs ----
    prep_a<<<dim3(32, 8, 127), 256>>>(q, k, v, w_qs, w_ks, w_vs,
                                      cq_b, ck_b, cv_b, bh, bl, fs + F_BIAS); // 1
    prep_b<<<21504, 256>>>(cq_w, ck_w, cv_w, fc_w, pj_w, bh, bl);             // 2

    // ---- 3. conv q/k/v MERGED: z1 = conv idx (0..2), z2 = batch ----
    gemm_tc<<<dim3(8, 2, 96), 256, GSMEM>>>(
        bh + O_WCQ, bl + O_WCQ, bh + O_QT, bl + O_QT,
        nullptr, bh + O_QB, bl + O_QB, 256, 256, 1024,
        851968, 0, 8486912, 265216, 8388608, 262144,
        0, 0, 0,
        65536, 256, 8, 13, 3, 32, 1.f, fs + F_BIAS, 256);

    // ---- 4. Q + K head projections MERGED: z3 = {q,k}, z1 = h, z2 = b ----
    gemm_tc<<<dim3(2, 2, 512), 256, GSMEM>>>(
        bh + O_QB, bl + O_QB, bh + O_WQT, bl + O_WQT,
        nullptr, bh + O_QS, bl + O_QS, 1024, 1024, 256,
        0, 262144, 262144, 0, 2097152, 65536,
        8388608, 2097152, 16777216,
        0, 0, 32, 1, 8, 32, 1.f, nullptr, 0);

    // ---- 5. V head projection, transposed output ----
    gemm_tc<<<dim3(2, 2, 256), 256, GSMEM>>>(
        bh + O_WVT, bl + O_WVT, bh + O_VB, bl + O_VB,
        nullptr, bh + O_VST, bl + O_VST, 1024, 1024, 256,
        262144, 0, 0, 262144, 2097152, 65536,
        0, 0, 0,
        0, 0, 32, 1, 8, 32, 1.f, nullptr, 0);

    // ---- 6. scores = qs . ks^T / 32 -> fp32 ----
    gemm_tc<<<dim3(2, 2, 256), 256, GSMEM>>>(
        bh + O_QS, bl + O_QS, bh + O_KS, bl + O_KS,
        fs + F_SC, nullptr, nullptr, 256, 256, 256,
        2097152, 65536, 2097152, 65536, 2097152, 65536,
        0, 0, 0,
        0, 0, 8, 1, 8, 32, 1.f / 32.f, nullptr, 0);

    // ---- 7. softmax -> attns (d_out) + split arena ----
    softmax_split<<<8192, 256>>>(fs + F_SC, attn, bh + O_ATT, bl + O_ATT);

    // ---- 8. out = attn . vsT^T -> cat (B, 256, 2048) ----
    gemm_tc<<<dim3(2, 2, 256), 256, GSMEM>>>(
        bh + O_ATT, bl + O_ATT, bh + O_VST, bl + O_VST,
        nullptr, bh + O_CAT, bl + O_CAT, 256, 256, 2048,
        2097152, 65536, 2097152, 65536, 256, 524288,
        0, 0, 0,
        0, 0, 8, 1, 8, 32, 1.f, nullptr, 0);

    // ---- 9. proj, transposed: C[dm][t] -> prT (pad row offset 6) ----
    gemm_tc<<<dim3(2, 8, 32), 256, GSMEM>>>(
        bh + O_PJW, bl + O_PJW, bh + O_CAT, bl + O_CAT,
        nullptr, bh + O_PRT + 1536, bl + O_PRT + 1536, 2048, 2048, 256,
        0, 0, 0, 524288, 0, 265216,
        0, 0, 0,
        0, 0, 64, 1, 1, 32, 1.f, pj_b, 0);

    // ---- 10. fc conv: M=256(o), N=1024(l), K=256 x 13 -> fp32 ----
    gemm_tc<<<dim3(8, 2, 32), 256, GSMEM>>>(
        bh + O_WFC, bl + O_WFC, bh + O_PRT, bl + O_PRT,
        fs + F_FC, nullptr, nullptr, 256, 256, 1024,
        0, 0, 0, 265216, 0, 262144,
        0, 0, 0,
        65536, 256, 8, 13, 1, 32, 1.f, fc_b, 0);

    // ---- 11. residual + LayerNorm ----
    ln_kernel<<<BATCH * DT, 256>>>(fs + F_FC, q, ln_a, ln_b, out);

    (void)in_sizes; (void)n_in; (void)out_size;
}

// round 16
// speedup vs baseline: 1.2520x; 1.1074x over previous
#include <cuda_runtime.h>
#include <cuda_bf16.h>
#include <math.h>

typedef __nv_bfloat16 bf16;
typedef long long ll;

#define NHEAD  8
#define DMODEL 1024
#define DT     256
#define BATCH  32
#define LLEN   1024

// ---------------------------------------------------------------------------
// Static arenas. hi/lo bf16 twins share offsets.
// ---------------------------------------------------------------------------
#define O_QT   0LL            // (32, 1036, 256) padded transposed inputs
#define O_KT   8486912LL
#define O_VT   16973824LL
#define O_PRT  25460736LL     // (32, 1036, 256) proj output, transposed+padded
#define O_WCQ  33947648LL     // conv weights repacked (13, 256, 256)
#define O_WCK  34799616LL
#define O_WCV  35651584LL
#define O_WFC  36503552LL
#define O_WQT  37355520LL     // head weights transposed (8, 256, 1024)
#define O_WKT  39452672LL
#define O_WVT  41549824LL
#define O_PJW  43646976LL     // proj weight (1024, 2048) split only
#define O_QB   45744128LL     // conv outputs (32, 256, 1024)
#define O_KB   54132736LL
#define O_VB   62521344LL
#define O_QS   70909952LL     // (8, 32, 256, 256)
#define O_KS   87687168LL
#define O_VST  104464384LL    // vs transposed (8, 32, 256(d), 256(t))
#define O_ATT  121241600LL
#define O_CAT  138018816LL    // (32, 256, 2048)
#define BF_TOTAL 154796032LL

#define F_SC   0LL
#define F_FC   16777216LL
#define F_BIAS 25165824LL     // packed conv biases (3 x 256)
#define F_TOTAL 25166848LL

__device__ __align__(1024) bf16  g_bh[BF_TOTAL];
__device__ __align__(1024) bf16  g_bl[BF_TOTAL];
__device__ __align__(1024) float g_fs[F_TOTAL];

// ---------------------------------------------------------------------------
// helpers (plain sm_80+ PTX: cp.async, ldmatrix, mma.sync)
// ---------------------------------------------------------------------------
__device__ __forceinline__ unsigned smem_u32(const void* p) {
    unsigned a;
    asm("{ .reg .u64 t; cvta.to.shared.u64 t, %1; cvt.u32.u64 %0, t; }"
        : "=r"(a) : "l"(p));
    return a;
}
__device__ __forceinline__ void cp16(unsigned dst, const void* src) {
    asm volatile("cp.async.cg.shared.global [%0], [%1], 16;"
                 :: "r"(dst), "l"(src) : "memory");
}
__device__ __forceinline__ void cp_commit() {
    asm volatile("cp.async.commit_group;" ::: "memory");
}
template <int N>
__device__ __forceinline__ void cp_wait() {
    asm volatile("cp.async.wait_group %0;" :: "n"(N) : "memory");
}
__device__ __forceinline__ void ldsm4(unsigned r[4], unsigned addr) {
    asm volatile("ldmatrix.sync.aligned.m8n8.x4.shared.b16 {%0,%1,%2,%3}, [%4];"
                 : "=r"(r[0]), "=r"(r[1]), "=r"(r[2]), "=r"(r[3]) : "r"(addr));
}
__device__ __forceinline__ void mma16816(float* c, const unsigned a[4],
                                         unsigned b0, unsigned b1) {
    asm volatile(
        "mma.sync.aligned.m16n8k16.row.col.f32.bf16.bf16.f32 "
        "{%0,%1,%2,%3}, {%4,%5,%6,%7}, {%8,%9}, {%0,%1,%2,%3};"
        : "+f"(c[0]), "+f"(c[1]), "+f"(c[2]), "+f"(c[3])
        : "r"(a[0]), "r"(a[1]), "r"(a[2]), "r"(a[3]), "r"(b0), "r"(b1));
}
__device__ __forceinline__ void split2(float x, bf16& h, bf16& l) {
    h = __float2bfloat16(x);
    l = __float2bfloat16(x - __bfloat162float(h));
}

// ---------------------------------------------------------------------------
// Universal split-bf16 NT GEMM, taps + 3-level batching.
//   z = (z3*Z1 + z1)*Z2 + z2
//   C[m,n] = alpha * sum_t sum_k A[t][m,k] * B[t][n,k] + bias_m[z1*bias_z + m]
// CTA tile 128x128, K-chunk 32, XOR-swizzled 64B smem rows.
// 3 stages, prefetch lead 1, SINGLE barrier per chunk (warp skew bounded to
// one chunk by the barrier; stages (i)%3, (i+1)%3, (i+2)%3 all distinct).
// Sub-tile 8KB, stage 32KB, 96KB total; 2 CTAs/SM, 8 warps (4m x 2n).
// ---------------------------------------------------------------------------
#define SUBT  8192
#define STG   32768
#define GSMEM (3 * STG)

__global__ __launch_bounds__(256, 2)
void gemm_tc(
    const bf16* __restrict__ Ahi, const bf16* __restrict__ Alo,
    const bf16* __restrict__ Bhi, const bf16* __restrict__ Blo,
    float* __restrict__ Cf, bf16* __restrict__ Chi, bf16* __restrict__ Clo,
    int lda, int ldb, int ldc,
    ll a1, ll a2, ll b1, ll b2, ll c1, ll c2,
    ll a3, ll b3, ll c3,
    ll a_tap, ll b_tap, int kc_per_tap, int taps, int Z1, int Z2,
    float alpha, const float* __restrict__ bias_m, ll bias_z)
{
    extern __shared__ __align__(128) char smem[];
    const unsigned sb0 = smem_u32(smem);
    const int tid = threadIdx.x;
    const int warp = tid >> 5, lane = tid & 31;
    const int z = blockIdx.z;
    const int zz = Z1 * Z2;
    const int z3 = z / zz;
    const int rem = z - z3 * zz;
    const int z1 = rem / Z2, z2 = rem - z1 * Z2;
    const int m0 = blockIdx.y * 128, n0 = blockIdx.x * 128;

    const ll aoff = (ll)z3 * a3 + (ll)z1 * a1 + (ll)z2 * a2 + (ll)m0 * lda;
    const ll boff = (ll)z3 * b3 + (ll)z1 * b1 + (ll)z2 * b2 + (ll)n0 * ldb;
    const bf16* pAh = Ahi + aoff;
    const bf16* pAl = Alo + aoff;
    const bf16* pBh = Bhi + boff;
    const bf16* pBl = Blo + boff;

    // cp.async store indexing: row = tid>>2 (+64), logical 16B col = tid&3,
    // physical col = c ^ ((row>>1)&3)  (same xor for row and row+64).
    const int ld_row = tid >> 2;
    const int ld_c16 = tid & 3;
    const int xo = (ld_row >> 1) & 3;
    const unsigned ld_off0 = (unsigned)(ld_row * 64 + ((ld_c16 ^ xo) << 4));
    const unsigned ld_off1 = (unsigned)((ld_row + 64) * 64 + ((ld_c16 ^ xo) << 4));

    float acc[2][8][4];
#pragma unroll
    for (int a = 0; a < 2; a++)
#pragma unroll
        for (int b = 0; b < 8; b++)
#pragma unroll
            for (int c = 0; c < 4; c++) acc[a][b][c] = 0.f;

    const int NC = kc_per_tap * taps;

    // division-free issue state (next chunk to fetch)
    int i_t = 0, i_kc = 0, i_stage = 0;
    auto issue = [&]() {
        const ll ao = (ll)i_t * a_tap + (ll)i_kc * 32 + (ll)ld_c16 * 8;
        const ll bo = (ll)i_t * b_tap + (ll)i_kc * 32 + (ll)ld_c16 * 8;
        const unsigned s = sb0 + (unsigned)i_stage * STG;
        const ll ar0 = (ll)ld_row * lda, ar1 = (ll)(ld_row + 64) * lda;
        const ll br0 = (ll)ld_row * ldb, br1 = (ll)(ld_row + 64) * ldb;
        cp16(s + ld_off0,             pAh + ao + ar0);
        cp16(s + ld_off1,             pAh + ao + ar1);
        cp16(s + SUBT + ld_off0,      pAl + ao + ar0);
        cp16(s + SUBT + ld_off1,      pAl + ao + ar1);
        cp16(s + 2 * SUBT + ld_off0,  pBh + bo + br0);
        cp16(s + 2 * SUBT + ld_off1,  pBh + bo + br1);
        cp16(s + 3 * SUBT + ld_off0,  pBl + bo + br0);
        cp16(s + 3 * SUBT + ld_off1,  pBl + bo + br1);
        cp_commit();
        if (++i_kc == kc_per_tap) { i_kc = 0; ++i_t; }
        if (++i_stage == 3) i_stage = 0;
    };

    const int wm = (warp & 3) * 32;       // warp m origin
    const int wn = (warp >> 2) * 64;      // warp n origin
    const int li = lane & 7, lj = lane >> 3;
    const int a_row_add = li + ((lj & 1) << 3);
    const int a_cadd    = lj >> 1;
    const int b_row_add = li + ((lj >> 1) << 3);
    const int b_cadd    = lj & 1;

    issue();                               // chunk 0
    int c_stage = 0;
    for (int i = 0; i < NC; i++) {
        if (i + 1 < NC) { issue(); cp_wait<1>(); }
        else            { cp_wait<0>(); }
        __syncthreads();                   // single barrier per chunk

        const unsigned s = sb0 + (unsigned)c_stage * STG;
        if (++c_stage == 3) c_stage = 0;
#pragma unroll
        for (int kk = 0; kk < 2; kk++) {
            unsigned ah[2][4], al[2][4];
#pragma unroll
            for (int mb = 0; mb < 2; mb++) {
                const int ar = wm + mb * 16 + a_row_add;
                const int ac = (kk * 2 + a_cadd) ^ ((ar >> 1) & 3);
                const unsigned aoffs = (unsigned)(ar * 64 + (ac << 4));
                ldsm4(ah[mb], s + aoffs);
                ldsm4(al[mb], s + SUBT + aoffs);
            }
#pragma unroll
            for (int nb = 0; nb < 4; nb++) {
                const int br = wn + nb * 16 + b_row_add;
                const int bc = (kk * 2 + b_cadd) ^ ((br >> 1) & 3);
                const unsigned boffs = (unsigned)(br * 64 + (bc << 4));
                unsigned bh[4], blr[4];
                ldsm4(bh,  s + 2 * SUBT + boffs);
                ldsm4(blr, s + 3 * SUBT + boffs);
                // product-interleaved: 4 independent accs between same-acc reuse
#pragma unroll
                for (int mb = 0; mb < 2; mb++)
#pragma unroll
                    for (int h = 0; h < 2; h++)
                        mma16816(acc[mb][nb * 2 + h], ah[mb], bh[2*h], bh[2*h+1]);
#pragma unroll
                for (int mb = 0; mb < 2; mb++)
#pragma unroll
                    for (int h = 0; h < 2; h++)
                        mma16816(acc[mb][nb * 2 + h], ah[mb], blr[2*h], blr[2*h+1]);
#pragma unroll
                for (int mb = 0; mb < 2; mb++)
#pragma unroll
                    for (int h = 0; h < 2; h++)
                        mma16816(acc[mb][nb * 2 + h], al[mb], bh[2*h], bh[2*h+1]);
            }
        }
    }

    // ---- epilogue ----
    const ll coff = (ll)z3 * c3 + (ll)z1 * c1 + (ll)z2 * c2;
    const ll boffb = (ll)z1 * bias_z;
    const int g = lane >> 2, qd = lane & 3;
#pragma unroll
    for (int mb = 0; mb < 2; mb++) {
        const int r0 = m0 + wm + mb * 16 + g;
        const float bm0 = bias_m ? bias_m[boffb + r0] : 0.f;
        const float bm1 = bias_m ? bias_m[boffb + r0 + 8] : 0.f;
#pragma unroll
        for (int nf = 0; nf < 8; nf++) {
            const int col = n0 + wn + nf * 8 + qd * 2;
            const float* c = acc[mb][nf];
            float v00 = c[0] * alpha + bm0, v01 = c[1] * alpha + bm0;
            float v10 = c[2] * alpha + bm1, v11 = c[3] * alpha + bm1;
            const ll o0 = coff + (ll)r0 * ldc + col;
            const ll o1 = coff + (ll)(r0 + 8) * ldc + col;
            if (Cf) {
                *reinterpret_cast<float2*>(Cf + o0) = make_float2(v00, v01);
                *reinterpret_cast<float2*>(Cf + o1) = make_float2(v10, v11);
            }
            if (Chi) {
                bf16 h0, l0, h1, l1;
                split2(v00, h0, l0); split2(v01, h1, l1);
                *reinterpret_cast<__nv_bfloat162*>(Chi + o0) = __nv_bfloat162(h0, h1);
                *reinterpret_cast<__nv_bfloat162*>(Clo + o0) = __nv_bfloat162(l0, l1);
                split2(v10, h0, l0); split2(v11, h1, l1);
                *reinterpret_cast<__nv_bfloat162*>(Chi + o1) = __nv_bfloat162(h0, h1);
                *reinterpret_cast<__nv_bfloat162*>(Clo + o1) = __nv_bfloat162(l0, l1);
            }
        }
    }
}

// ---------------------------------------------------------------------------
// PREP A (launch #1): input transposes (z<96), weight transposes (96<=z<120),
// halo-pad zeroing + bias packing (z>=120). grid (32, 8, 127) x 256.
// ---------------------------------------------------------------------------
__global__ __launch_bounds__(256) void prep_a(
    const float* __restrict__ q, const float* __restrict__ k,
    const float* __restrict__ v,
    const float* __restrict__ wq, const float* __restrict__ wk,
    const float* __restrict__ wv,
    const float* __restrict__ b0, const float* __restrict__ b1,
    const float* __restrict__ b2,
    bf16* __restrict__ oh, bf16* __restrict__ ol, float* __restrict__ ob)
{
    const int zb = blockIdx.z;
    const int tx = threadIdx.x & 31, ty = threadIdx.x >> 5;
    __shared__ float t[32][33];

    if (zb < 96) {               // inputs: (32,256,1024) -> (32,1036,256)+6
        const int sel = zb >> 5, b = zb & 31;
        const float* in = (sel == 0 ? q : sel == 1 ? k : v) + (size_t)b * 262144;
        const size_t obase = (size_t)sel * 8486912 + (size_t)b * 265216;
        const int c0 = blockIdx.x * 32, r0 = blockIdx.y * 32;
#pragma unroll
        for (int j = 0; j < 4; j++)
            t[ty + 8 * j][tx] = in[(size_t)(r0 + ty + 8 * j) * 1024 + c0 + tx];
        __syncthreads();
#pragma unroll
        for (int j = 0; j < 4; j++) {
            float x = t[tx][ty + 8 * j];
            bf16 h, l; split2(x, h, l);
            size_t o = obase + (size_t)(c0 + ty + 8 * j + 6) * 256 + r0 + tx;
            (oh + O_QT)[o] = h; (ol + O_QT)[o] = l;
        }
    } else if (zb < 120) {       // head weights: (8,1024,256) -> (8,256,1024)
        const int zw = zb - 96;
        const int sel = zw >> 3, hh = zw & 7;
        const float* in = (sel == 0 ? wq : sel == 1 ? wk : wv) + (size_t)hh * 262144;
        const size_t obase = (size_t)sel * 2097152 + (size_t)hh * 262144;
        const int tlin = blockIdx.x * 8 + blockIdx.y;     // 0..255
        const int c0 = (tlin & 7) * 32, r0 = (tlin >> 3) * 32;
#pragma unroll
        for (int j = 0; j < 4; j++)
            t[ty + 8 * j][tx] = in[(size_t)(r0 + ty + 8 * j) * 256 + c0 + tx];
        __syncthreads();
#pragma unroll
        for (int j = 0; j < 4; j++) {
            float x = t[tx][ty + 8 * j];
            bf16 h, l; split2(x, h, l);
            size_t o = obase + (size_t)(c0 + ty + 8 * j) * 1024 + r0 + tx;
            (oh + O_WQT)[o] = h; (ol + O_WQT)[o] = l;
        }
    } else {                      // pads + bias, 1D
        const int blin = blockIdx.y * 32 + blockIdx.x;    // 0..255
        const int idx = ((zb - 120) * 256 + blin) * 256 + threadIdx.x;
        if (idx < 393216) {
            int b = idx / 3072, rem2 = idx % 3072;
            int r12 = rem2 >> 8, c = rem2 & 255;
            int row = (r12 < 6) ? r12 : (1024 + r12);
            size_t o = (size_t)b * 265216 + (size_t)row * 256 + c;
            (oh + O_QT)[o] = __float2bfloat16(0.f);
            (ol + O_QT)[o] = __float2bfloat16(0.f);
        } else if (idx < 393984) {
            int i = idx - 393216;
            int sel = i >> 8, c = i & 255;
            ob[i] = (sel == 0 ? b0 : sel == 1 ? b1 : b2)[c];
        }
    }
}

// ---------------------------------------------------------------------------
// PREP B (launch #2): conv-weight repack (4 tensors) + proj-weight split.
// ---------------------------------------------------------------------------
__global__ __launch_bounds__(256) void prep_b(
    const float* __restrict__ w0, const float* __restrict__ w1,
    const float* __restrict__ w2, const float* __restrict__ w3,
    const float* __restrict__ pw,
    bf16* __restrict__ oh, bf16* __restrict__ ol)
{
    int idx = blockIdx.x * 256 + threadIdx.x;
    if (idx < 3407872) {
        int sel = idx / 851968, r = idx - sel * 851968;
        int t = r >> 16, rem = r & 65535;
        int o = rem >> 8, c = rem & 255;
        const float* w = sel == 0 ? w0 : sel == 1 ? w1 : sel == 2 ? w2 : w3;
        float x = w[(size_t)(o * 256 + c) * 13 + t];
        bf16 h, l; split2(x, h, l);
        (oh + O_WCQ)[idx] = h; (ol + O_WCQ)[idx] = l;
    } else {
        int i = idx - 3407872;
        if (i < 2097152) {
            bf16 h, l; split2(pw[i], h, l);
            (oh + O_PJW)[i] = h; (ol + O_PJW)[i] = l;
        }
    }
}

// ---------------------------------------------------------------------------
// softmax over last axis (256); fp32 attn to d_out AND split pair to arena.
// ---------------------------------------------------------------------------
__global__ __launch_bounds__(256) void softmax_split(
    const float* __restrict__ scores, float* __restrict__ attn,
    bf16* __restrict__ ah, bf16* __restrict__ al)
{
    const int row  = blockIdx.x * 8 + (threadIdx.x >> 5);
    const int lane = threadIdx.x & 31;
    const float* s = scores + (size_t)row * 256;

    float v[8];
    float mx = -1e30f;
#pragma unroll
    for (int j = 0; j < 8; j++) { v[j] = s[lane + 32 * j]; mx = fmaxf(mx, v[j]); }
#pragma unroll
    for (int o = 16; o; o >>= 1) mx = fmaxf(mx, __shfl_xor_sync(0xffffffffu, mx, o));
    float sum = 0.f;
#pragma unroll
    for (int j = 0; j < 8; j++) { v[j] = expf(v[j] - mx); sum += v[j]; }
#pragma unroll
    for (int o = 16; o; o >>= 1) sum += __shfl_xor_sync(0xffffffffu, sum, o);
    const float inv = 1.f / sum;

    float* a  = attn + (size_t)row * 256;
    bf16* hh = ah + (size_t)row * 256;
    bf16* ll_ = al + (size_t)row * 256;
#pragma unroll
    for (int j = 0; j < 8; j++) {
        float p = v[j] * inv;
        a[lane + 32 * j] = p;
        bf16 h, l; split2(p, h, l);
        hh[lane + 32 * j] = h; ll_[lane + 32 * j] = l;
    }
}

// ---------------------------------------------------------------------------
// residual + LayerNorm (ddof=1, eps added to sigma)
// ---------------------------------------------------------------------------
__global__ __launch_bounds__(256) void ln_kernel(
    const float* __restrict__ fc, const float* __restrict__ q,
    const float* __restrict__ ga, const float* __restrict__ gb,
    float* __restrict__ out)
{
    const int row = blockIdx.x;
    const float* f  = fc + (size_t)row * DMODEL;
    const float* qq = q  + (size_t)row * DMODEL;
    const int tid = threadIdx.x;

    float zv[4];
    float s = 0.f, ss = 0.f;
#pragma unroll
    for (int j = 0; j < 4; j++) {
        float zz = f[tid + 256 * j] + qq[tid + 256 * j];
        zv[j] = zz; s += zz; ss += zz * zz;
    }
    __shared__ float rs[8], rss[8];
#pragma unroll
    for (int o = 16; o; o >>= 1) {
        s  += __shfl_xor_sync(0xffffffffu, s, o);
        ss += __shfl_xor_sync(0xffffffffu, ss, o);
    }
    if ((tid & 31) == 0) { rs[tid >> 5] = s; rss[tid >> 5] = ss; }
    __syncthreads();
    if (tid < 32) {
        float a = (tid < 8) ? rs[tid] : 0.f;
        float b = (tid < 8) ? rss[tid] : 0.f;
#pragma unroll
        for (int o = 4; o; o >>= 1) {
            a += __shfl_xor_sync(0xffffffffu, a, o);
            b += __shfl_xor_sync(0xffffffffu, b, o);
        }
        if (tid == 0) { rs[0] = a; rss[0] = b; }
    }
    __syncthreads();
    const float mu  = rs[0] * (1.f / DMODEL);
    const float var = (rss[0] - (float)DMODEL * mu * mu) * (1.f / (DMODEL - 1));
    const float inv = 1.f / (sqrtf(fmaxf(var, 0.f)) + 1e-3f);
    float* o_ = out + (size_t)row * DMODEL;
#pragma unroll
    for (int j = 0; j < 4; j++) {
        const int col = tid + 256 * j;
        o_[col] = (zv[j] - mu) * inv * ga[col] + gb[col];
    }
}

// ---------------------------------------------------------------------------
extern "C" void kernel_launch(void* const* d_in, const int* in_sizes, int n_in,
                              void* d_out, int out_size)
{
    const float* q    = (const float*)d_in[0];
    const float* k    = (const float*)d_in[1];
    const float* v    = (const float*)d_in[2];
    const float* cq_w = (const float*)d_in[3];
    const float* cq_b = (const float*)d_in[4];
    const float* ck_w = (const float*)d_in[5];
    const float* ck_b = (const float*)d_in[6];
    const float* cv_w = (const float*)d_in[7];
    const float* cv_b = (const float*)d_in[8];
    const float* w_qs = (const float*)d_in[9];
    const float* w_ks = (const float*)d_in[10];
    const float* w_vs = (const float*)d_in[11];
    const float* pj_w = (const float*)d_in[12];
    const float* pj_b = (const float*)d_in[13];
    const float* fc_w = (const float*)d_in[14];
    const float* fc_b = (const float*)d_in[15];
    const float* ln_a = (const float*)d_in[16];
    const float* ln_b = (const float*)d_in[17];

    bf16 *bh = nullptr, *bl = nullptr; float* fs = nullptr;
    cudaGetSymbolAddress((void**)&bh, g_bh);
    cudaGetSymbolAddress((void**)&bl, g_bl);
    cudaGetSymbolAddress((void**)&fs, g_fs);

    cudaFuncSetAttribute(gemm_tc, cudaFuncAttributeMaxDynamicSharedMemorySize, GSMEM);

    float* out  = (float*)d_out;
    float* attn = out + (size_t)BATCH * DT * LLEN;

    // ---- preps: exactly 2 launches; all subsequent launches are GEMMs ----
    prep_a<<<dim3(32, 8, 127), 256>>>(q, k, v, w_qs, w_ks, w_vs,
                                      cq_b, ck_b, cv_b, bh, bl, fs + F_BIAS); // 1
    prep_b<<<21504, 256>>>(cq_w, ck_w, cv_w, fc_w, pj_w, bh, bl);             // 2

    // ---- 3. conv q/k/v MERGED: z1 = conv idx (0..2), z2 = batch ----
    gemm_tc<<<dim3(8, 2, 96), 256, GSMEM>>>(
        bh + O_WCQ, bl + O_WCQ, bh + O_QT, bl + O_QT,
        nullptr, bh + O_QB, bl + O_QB, 256, 256, 1024,
        851968, 0, 8486912, 265216, 8388608, 262144,
        0, 0, 0,
        65536, 256, 8, 13, 3, 32, 1.f, fs + F_BIAS, 256);

    // ---- 4. Q + K head projections MERGED: z3 = {q,k}, z1 = h, z2 = b ----
    gemm_tc<<<dim3(2, 2, 512), 256, GSMEM>>>(
        bh + O_QB, bl + O_QB, bh + O_WQT, bl + O_WQT,
        nullptr, bh + O_QS, bl + O_QS, 1024, 1024, 256,
        0, 262144, 262144, 0, 2097152, 65536,
        8388608, 2097152, 16777216,
        0, 0, 32, 1, 8, 32, 1.f, nullptr, 0);

    // ---- 5. V head projection, transposed output ----
    gemm_tc<<<dim3(2, 2, 256), 256, GSMEM>>>(
        bh + O_WVT, bl + O_WVT, bh + O_VB, bl + O_VB,
        nullptr, bh + O_VST, bl + O_VST, 1024, 1024, 256,
        262144, 0, 0, 262144, 2097152, 65536,
        0, 0, 0,
        0, 0, 32, 1, 8, 32, 1.f, nullptr, 0);

    // ---- 6. scores = qs . ks^T / 32 -> fp32 ----
    gemm_tc<<<dim3(2, 2, 256), 256, GSMEM>>>(
        bh + O_QS, bl + O_QS, bh + O_KS, bl + O_KS,
        fs + F_SC, nullptr, nullptr, 256, 256, 256,
        2097152, 65536, 2097152, 65536, 2097152, 65536,
        0, 0, 0,
        0, 0, 8, 1, 8, 32, 1.f / 32.f, nullptr, 0);

    // ---- 7. softmax -> attns (d_out) + split arena ----
    softmax_split<<<8192, 256>>>(fs + F_SC, attn, bh + O_ATT, bl + O_ATT);

    // ---- 8. out = attn . vsT^T -> cat (B, 256, 2048) ----
    gemm_tc<<<dim3(2, 2, 256), 256, GSMEM>>>(
        bh + O_ATT, bl + O_ATT, bh + O_VST, bl + O_VST,
        nullptr, bh + O_CAT, bl + O_CAT, 256, 256, 2048,
        2097152, 65536, 2097152, 65536, 256, 524288,
        0, 0, 0,
        0, 0, 8, 1, 8, 32, 1.f, nullptr, 0);

    // ---- 9. proj, transposed: C[dm][t] -> prT (pad row offset 6) ----
    gemm_tc<<<dim3(2, 8, 32), 256, GSMEM>>>(
        bh + O_PJW, bl + O_PJW, bh + O_CAT, bl + O_CAT,
        nullptr, bh + O_PRT + 1536, bl + O_PRT + 1536, 2048, 2048, 256,
        0, 0, 0, 524288, 0, 265216,
        0, 0, 0,
        0, 0, 64, 1, 1, 32, 1.f, pj_b, 0);

    // ---- 10. fc conv: M=256(o), N=1024(l), K=256 x 13 -> fp32 ----
    gemm_tc<<<dim3(8, 2, 32), 256, GSMEM>>>(
        bh + O_WFC, bl + O_WFC, bh + O_PRT, bl + O_PRT,
        fs + F_FC, nullptr, nullptr, 256, 256, 1024,
        0, 0, 0, 265216, 0, 262144,
        0, 0, 0,
        65536, 256, 8, 13, 1, 32, 1.f, fc_b, 0);

    // ---- 11. residual + LayerNorm ----
    ln_kernel<<<BATCH * DT, 256>>>(fs + F_FC, q, ln_a, ln_b, out);

    (void)in_sizes; (void)n_in; (void)out_size;
}